// round 3
// baseline (speedup 1.0000x reference)
#include <cuda_runtime.h>
#include <math.h>

#define NN 4096
#define EE 32768
#define EC 4096          // edges per chunk (w-chunk = 56.6 MB, L2-resident)
#define NCHUNK (EE / EC)
#define BBATCH 16
#define LL 4

#define SQ3C     1.73205080757f
#define SQ5C     2.23606797750f
#define INV_SQ3  0.57735026919f
#define INV_SQ5  0.44721359550f
#define INV_SQ75 0.36514837167f
#define A0C      0.13363062095f
#define A1C      0.20412414523f
#define A2C      0.27950849719f
#define ISQ32    0.17677669530f
#define ISQ16    0.25f
#define ISQ8     0.35355339059f
#define RBFN     0.79788458f

__constant__ float cQ[5][9] = {
    {0.f, 0.f, 0.86602540378f,  0.f, 0.f, 0.f,  0.86602540378f, 0.f, 0.f},
    {0.f, 0.86602540378f, 0.f,  0.86602540378f, 0.f, 0.f,  0.f, 0.f, 0.f},
    {-0.5f, 0.f, 0.f,  0.f, 1.f, 0.f,  0.f, 0.f, -0.5f},
    {0.f, 0.f, 0.f,  0.f, 0.f, 0.86602540378f,  0.f, 0.86602540378f, 0.f},
    {-0.86602540378f, 0.f, 0.f,  0.f, 0.f, 0.f,  0.f, 0.f, 0.86602540378f}};

__device__ float g_s1[EE * 3];
__device__ float g_s2[EE * 5];
__device__ float g_rbf[EE * 8];
__device__ float g_hid[EE * 64];
__device__ float g_w[(size_t)EC * 3456];
__device__ float g_h0[2][NN * 32];
__device__ float g_h1[2][NN * 48];
__device__ float g_h2[2][NN * 40];
__device__ float g_agg0[NN * 32];
__device__ float g_agg1[NN * 48];
__device__ float g_agg2[NN * 40];
__device__ float g_att[NN];
__device__ float g_pool[BBATCH * 32];
__device__ float g_C222[125];

__device__ __forceinline__ float siluf(float x) { return x / (1.f + expf(-x)); }

__global__ void k_init_cg() {
    if (threadIdx.x != 0 || blockIdx.x != 0) return;
    float T[125];
    float nrm = 0.f;
    for (int i = 0; i < 5; i++)
        for (int j = 0; j < 5; j++)
            for (int k = 0; k < 5; k++) {
                float s = 0.f;
                for (int a = 0; a < 3; a++)
                    for (int b = 0; b < 3; b++)
                        for (int c = 0; c < 3; c++)
                            s += cQ[i][a * 3 + b] * cQ[j][b * 3 + c] * cQ[k][c * 3 + a];
                T[(i * 5 + j) * 5 + k] = s;
                nrm += s * s;
            }
    nrm = sqrtf(nrm);
    for (int t = 0; t < 125; t++) g_C222[t] = T[t] / nrm;
}

__global__ void k_edge_geom(const float* __restrict__ pos, const int* __restrict__ ei) {
    int e = blockIdx.x * 256 + threadIdx.x;
    if (e >= EE) return;
    int s = ei[e], d = ei[EE + e];
    float rx = pos[d * 3 + 0] - pos[s * 3 + 0];
    float ry = pos[d * 3 + 1] - pos[s * 3 + 1];
    float rz = pos[d * 3 + 2] - pos[s * 3 + 2];
    float dist = sqrtf(rx * rx + ry * ry + rz * rz);
    dist = fmaxf(dist, 1e-6f);
    float nx = rx / dist, ny = ry / dist, nz = rz / dist;
    g_s1[e * 3 + 0] = SQ3C * nx;
    g_s1[e * 3 + 1] = SQ3C * ny;
    g_s1[e * 3 + 2] = SQ3C * nz;
    g_s2[e * 5 + 0] = SQ5C * (SQ3C * nx * nz);
    g_s2[e * 5 + 1] = SQ5C * (SQ3C * nx * ny);
    g_s2[e * 5 + 2] = SQ5C * (ny * ny - 0.5f * (nx * nx + nz * nz));
    g_s2[e * 5 + 3] = SQ5C * (SQ3C * ny * nz);
    g_s2[e * 5 + 4] = SQ5C * (0.5f * SQ3C * (nz * nz - nx * nx));
#pragma unroll
    for (int i = 0; i < 8; i++) {
        float c = 6.f * (float)i / 7.f;
        float t = dist - c;
        g_rbf[e * 8 + i] = expf(-2.f * t * t) * RBFN;
    }
}

__global__ void k_embed(const float* __restrict__ x, const float* __restrict__ W) {
    int n = blockIdx.x;
    int v = threadIdx.x;
    __shared__ float xr[64];
    for (int i = v; i < 64; i += 32) xr[i] = x[n * 64 + i];
    __syncthreads();
    float s = 0.f;
#pragma unroll 8
    for (int c = 0; c < 64; c++) s += xr[c] * W[c * 32 + v];
    g_h0[0][n * 32 + v] = s * 0.125f;
}

__global__ void k_zero_h() {
    int i = blockIdx.x * 256 + threadIdx.x;
    if (i < NN * 48) g_h1[0][i] = 0.f;
    if (i < NN * 40) g_h2[0][i] = 0.f;
}

__global__ void k_zero_agg() {
    int i = blockIdx.x * 256 + threadIdx.x;
    if (i < NN * 32) g_agg0[i] = 0.f;
    if (i < NN * 48) g_agg1[i] = 0.f;
    if (i < NN * 40) g_agg2[i] = 0.f;
}

__global__ void k_radial(const float* __restrict__ W1, const float* __restrict__ b1,
                         const float* __restrict__ W2, const float* __restrict__ b2) {
    int le = threadIdx.x >> 6;
    int t = threadIdx.x & 63;
    int e = blockIdx.x * 4 + le;
    __shared__ float sh[4][64];
    const float* r = g_rbf + e * 8;
    float z = b1[t];
#pragma unroll
    for (int i = 0; i < 8; i++) z += r[i] * W1[i * 64 + t];
    sh[le][t] = siluf(z);
    __syncthreads();
    float z2 = b2[t];
#pragma unroll 8
    for (int i = 0; i < 64; i++) z2 += sh[le][i] * W2[i * 64 + t];
    g_hid[e * 64 + t] = siluf(z2);
}

__global__ void __launch_bounds__(256) k_gemm_chunk(int chunk,
                                                    const float* __restrict__ Bm,
                                                    const float* __restrict__ bias) {
    __shared__ float As[64][128];
    __shared__ float Bs[16][128];
    int bx = blockIdx.x, by = blockIdx.y;
    int tid = threadIdx.x;
    int tx = tid & 15, ty = tid >> 4;
    const float* Ab = g_hid + (size_t)(chunk * EC + by * 128) * 64;
    const float* Bb = Bm + bx * 128;

    {
        int ar = tid >> 1, ah = (tid & 1) * 32;
#pragma unroll
        for (int q = 0; q < 8; q++) {
            float4 v = *(const float4*)(Ab + ar * 64 + ah + q * 4);
            As[ah + q * 4 + 0][ar] = v.x;
            As[ah + q * 4 + 1][ar] = v.y;
            As[ah + q * 4 + 2][ar] = v.z;
            As[ah + q * 4 + 3][ar] = v.w;
        }
    }

    float acc[8][8];
#pragma unroll
    for (int i = 0; i < 8; i++)
#pragma unroll
        for (int j = 0; j < 8; j++) acc[i][j] = 0.f;

    int bk = tid >> 4, bn = (tid & 15) * 8;

    for (int k0 = 0; k0 < 64; k0 += 16) {
        __syncthreads();
        *(float4*)&Bs[bk][bn]     = *(const float4*)(Bb + (size_t)(k0 + bk) * 3456 + bn);
        *(float4*)&Bs[bk][bn + 4] = *(const float4*)(Bb + (size_t)(k0 + bk) * 3456 + bn + 4);
        __syncthreads();
#pragma unroll
        for (int kk = 0; kk < 16; kk++) {
            float a[8], b[8];
            *(float4*)&a[0] = *(float4*)&As[k0 + kk][ty * 8];
            *(float4*)&a[4] = *(float4*)&As[k0 + kk][ty * 8 + 4];
            *(float4*)&b[0] = *(float4*)&Bs[kk][tx * 8];
            *(float4*)&b[4] = *(float4*)&Bs[kk][tx * 8 + 4];
#pragma unroll
            for (int i = 0; i < 8; i++)
#pragma unroll
                for (int j = 0; j < 8; j++) acc[i][j] += a[i] * b[j];
        }
    }
    float bvec[8];
#pragma unroll
    for (int j = 0; j < 8; j++) bvec[j] = bias[bx * 128 + tx * 8 + j];
#pragma unroll
    for (int i = 0; i < 8; i++) {
        size_t row = ((size_t)(by * 128 + ty * 8 + i)) * 3456 + bx * 128 + tx * 8;
        float4 c0, c1;
        c0.x = acc[i][0] + bvec[0]; c0.y = acc[i][1] + bvec[1];
        c0.z = acc[i][2] + bvec[2]; c0.w = acc[i][3] + bvec[3];
        c1.x = acc[i][4] + bvec[4]; c1.y = acc[i][5] + bvec[5];
        c1.z = acc[i][6] + bvec[6]; c1.w = acc[i][7] + bvec[7];
        *(float4*)(g_w + row) = c0;
        *(float4*)(g_w + row + 4) = c1;
    }
}

__global__ void __launch_bounds__(256) k_msg(int cur, int e0, const int* __restrict__ ei) {
    __shared__ float S[8][400];
    int wid = threadIdx.x >> 5, lane = threadIdx.x & 31;
    int e = e0 + blockIdx.x * 8 + wid;
    float* P = S[wid];
    int src = ei[e], dst = ei[EE + e];
    const float* h0 = g_h0[cur];
    const float* h1 = g_h1[cur];
    const float* h2 = g_h2[cur];

    if (lane < 32) P[lane] = h0[src * 32 + lane];
    for (int i = lane; i < 48; i += 32) P[32 + i] = h1[src * 48 + i];
    for (int i = lane; i < 40; i += 32) P[80 + i] = h2[src * 40 + i];
    if (lane < 3) P[336 + lane] = g_s1[e * 3 + lane];
    if (lane < 5) P[339 + lane] = g_s2[e * 5 + lane];
    __syncwarp();

    if (lane < 9) {
        int i = lane / 3, j = lane % 3;
        float s = 0.f;
#pragma unroll
        for (int k = 0; k < 5; k++) s += P[339 + k] * cQ[k][i * 3 + j];
        P[344 + lane] = s;
    } else if (lane < 24) {
        int idx = lane - 9;
        int a = idx / 3, c = idx % 3;
        float s = 0.f;
#pragma unroll
        for (int b = 0; b < 3; b++) s += cQ[a][b * 3 + c] * P[336 + b];
        P[353 + idx] = s;
    } else {
        int u = lane - 24;
        float s = 0.f;
#pragma unroll
        for (int k = 0; k < 5; k++) s += P[80 + u * 5 + k] * P[339 + k];
        P[136 + u] = s * INV_SQ5;
    }
    __syncwarp();
    if (lane < 25) {
        int a = lane / 5, k = lane % 5;
        float s = 0.f;
#pragma unroll
        for (int b = 0; b < 5; b++) s += P[339 + b] * g_C222[(a * 5 + b) * 5 + k];
        P[368 + lane] = s;
    } else {
        int u = lane - 25;
        float s = 0.f;
#pragma unroll
        for (int i = 0; i < 3; i++) s += P[32 + u * 3 + i] * P[336 + i];
        P[120 + u] = s * INV_SQ3;
    }
    __syncwarp();
    if (lane < 9) {
        int u = lane + 7;
        float s = 0.f;
#pragma unroll
        for (int i = 0; i < 3; i++) s += P[32 + u * 3 + i] * P[336 + i];
        P[120 + u] = s * INV_SQ3;
    }
    __syncwarp();

    for (int idx = lane; idx < 192; idx += 32) {
        if (idx < 48) {
            int u = idx / 3, j = idx % 3;
            float s = 0.f;
#pragma unroll
            for (int i = 0; i < 3; i++) s += P[32 + u * 3 + i] * P[344 + i * 3 + j];
            P[144 + idx] = s * INV_SQ75;
        } else if (idx < 72) {
            int t = idx - 48;
            int u = t / 3, c = t % 3;
            float s = 0.f;
#pragma unroll
            for (int a = 0; a < 5; a++) s += P[80 + u * 5 + a] * P[353 + a * 3 + c];
            P[192 + t] = s * INV_SQ75;
        } else if (idx < 152) {
            int t = idx - 72;
            int u = t / 5, k = t % 5;
            float s = 0.f;
#pragma unroll
            for (int i = 0; i < 3; i++) s += P[32 + u * 3 + i] * P[353 + k * 3 + i];
            P[216 + t] = s * INV_SQ75;
        } else {
            int t = idx - 152;
            int u = t / 5, k = t % 5;
            float s = 0.f;
#pragma unroll
            for (int a = 0; a < 5; a++) s += P[80 + u * 5 + a] * P[368 + a * 5 + k];
            P[296 + t] = s;
        }
    }
    __syncwarp();

    const float* w = g_w + (size_t)(e - e0) * 3456;
    {
        int v = lane;
        float acc = 0.f;
#pragma unroll 8
        for (int u = 0; u < 32; u++) acc += w[u * 32 + v] * P[u];
#pragma unroll 8
        for (int u = 0; u < 16; u++) acc += w[1024 + u * 32 + v] * P[120 + u];
#pragma unroll
        for (int u = 0; u < 8; u++) acc += w[1536 + u * 32 + v] * P[136 + u];
        atomicAdd(&g_agg0[dst * 32 + v], A0C * acc);
    }
    if (lane < 16) {
        int v = lane;
        float p011 = 0.f;
#pragma unroll 8
        for (int u = 0; u < 32; u++) p011 += w[1792 + u * 16 + v] * P[u];
        float a1c[3] = {0.f, 0.f, 0.f};
        float b1c[3] = {0.f, 0.f, 0.f};
#pragma unroll 4
        for (int u = 0; u < 16; u++) {
            float wa = w[2304 + u * 16 + v];
            float wb = w[2560 + u * 16 + v];
#pragma unroll
            for (int j = 0; j < 3; j++) {
                a1c[j] += wa * P[32 + u * 3 + j];
                b1c[j] += wb * P[144 + u * 3 + j];
            }
        }
#pragma unroll
        for (int u = 0; u < 8; u++) {
            float wc = w[2816 + u * 16 + v];
#pragma unroll
            for (int j = 0; j < 3; j++) b1c[j] += wc * P[192 + u * 3 + j];
        }
#pragma unroll
        for (int j = 0; j < 3; j++) {
            float m = A1C * ((p011 * P[336 + j] + a1c[j]) * INV_SQ3 + b1c[j]);
            atomicAdd(&g_agg1[dst * 48 + v * 3 + j], m);
        }
    }
    if (lane < 8) {
        int v = lane;
        float p022 = 0.f;
#pragma unroll 8
        for (int u = 0; u < 32; u++) p022 += w[2944 + u * 8 + v] * P[u];
        float t2c[5] = {0.f, 0.f, 0.f, 0.f, 0.f};
#pragma unroll 4
        for (int u = 0; u < 16; u++) {
            float wa = w[3200 + u * 8 + v];
#pragma unroll
            for (int k = 0; k < 5; k++) t2c[k] += wa * P[216 + u * 5 + k];
        }
#pragma unroll
        for (int u = 0; u < 8; u++) {
            float wb = w[3328 + u * 8 + v];
            float wc = w[3392 + u * 8 + v];
#pragma unroll
            for (int k = 0; k < 5; k++)
                t2c[k] += wb * P[80 + u * 5 + k] * INV_SQ5 + wc * P[296 + u * 5 + k];
        }
#pragma unroll
        for (int k = 0; k < 5; k++) {
            float m = A2C * (p022 * P[339 + k] * INV_SQ5 + t2c[k]);
            atomicAdd(&g_agg2[dst * 40 + v * 5 + k], m);
        }
    }
}

__global__ void k_si(int cur, const float* __restrict__ siW0, const float* __restrict__ siW1,
                     const float* __restrict__ siW2) {
    int n = blockIdx.x, t = threadIdx.x;
    int nxt = cur ^ 1;
    __shared__ float o0[32], o1[48], o2[40];
    if (t < 32) o0[t] = g_h0[cur][n * 32 + t];
    else if (t < 80) o1[t - 32] = g_h1[cur][n * 48 + (t - 32)];
    else if (t < 120) o2[t - 80] = g_h2[cur][n * 40 + (t - 80)];
    __syncthreads();
    if (t < 32) {
        float s = 0.f;
#pragma unroll 8
        for (int u = 0; u < 32; u++) s += o0[u] * siW0[u * 32 + t];
        g_h0[nxt][n * 32 + t] = s * ISQ32 + g_agg0[n * 32 + t];
    } else if (t < 80) {
        int idx = t - 32;
        int v = idx / 3, i = idx % 3;
        float s = 0.f;
#pragma unroll 4
        for (int u = 0; u < 16; u++) s += o1[u * 3 + i] * siW1[u * 16 + v];
        g_h1[nxt][n * 48 + idx] = s * ISQ16 + g_agg1[n * 48 + idx];
    } else if (t < 120) {
        int idx = t - 80;
        int v = idx / 5, k = idx % 5;
        float s = 0.f;
#pragma unroll
        for (int u = 0; u < 8; u++) s += o2[u * 5 + k] * siW2[u * 8 + v];
        g_h2[nxt][n * 40 + idx] = s * ISQ8 + g_agg2[n * 40 + idx];
    }
}

__global__ void k_attmlp(const float* __restrict__ W1, const float* __restrict__ b1,
                         const float* __restrict__ W2, const float* __restrict__ b2,
                         const float* __restrict__ W3, const float* __restrict__ b3) {
    int n = blockIdx.x, t = threadIdx.x;
    __shared__ float hr[32], a1[128], red[128];
    if (t < 32) hr[t] = g_h0[0][n * 32 + t];
    __syncthreads();
    float z = b1[t];
#pragma unroll 8
    for (int c = 0; c < 32; c++) z += hr[c] * W1[c * 128 + t];
    a1[t] = siluf(z);
    __syncthreads();
    float z2 = b2[t];
#pragma unroll 8
    for (int c = 0; c < 128; c++) z2 += a1[c] * W2[c * 128 + t];
    z2 = siluf(z2);
    red[t] = z2 * W3[t];
    __syncthreads();
    for (int s = 64; s > 0; s >>= 1) {
        if (t < s) red[t] += red[t + s];
        __syncthreads();
    }
    if (t == 0) g_att[n] = red[0] + b3[0];
}

__global__ void k_pool(const int* __restrict__ batch) {
    int b = blockIdx.x, tid = threadIdx.x;
    __shared__ float red[256];
    __shared__ float gacc[32];
    __shared__ float s_amax, s_den;
    float lm = -1e30f;
    for (int n = tid; n < NN; n += 256)
        if (batch[n] == b) lm = fmaxf(lm, g_att[n]);
    red[tid] = lm;
    __syncthreads();
    for (int s = 128; s > 0; s >>= 1) {
        if (tid < s) red[tid] = fmaxf(red[tid], red[tid + s]);
        __syncthreads();
    }
    if (tid == 0) s_amax = red[0];
    if (tid < 32) gacc[tid] = 0.f;
    __syncthreads();
    float amax = s_amax;
    float lden = 0.f;
    for (int n = tid; n < NN; n += 256)
        if (batch[n] == b) {
            float ex = expf(g_att[n] - amax);
            lden += ex;
#pragma unroll
            for (int c = 0; c < 32; c++) atomicAdd(&gacc[c], ex * g_h0[0][n * 32 + c]);
        }
    red[tid] = lden;
    __syncthreads();
    for (int s = 128; s > 0; s >>= 1) {
        if (tid < s) red[tid] += red[tid + s];
        __syncthreads();
    }
    if (tid == 0) s_den = red[0];
    __syncthreads();
    if (tid < 32) g_pool[b * 32 + tid] = gacc[tid] / s_den;
}

__global__ void k_out(const float* __restrict__ W, const float* __restrict__ bo,
                      const float* __restrict__ lg, const float* __restrict__ lb,
                      float* __restrict__ out) {
    int b = blockIdx.x, j = threadIdx.x;
    __shared__ float gr[32];
    __shared__ float red[512];
    if (j < 32) gr[j] = g_pool[b * 32 + j];
    __syncthreads();
    float o = bo[j];
#pragma unroll 8
    for (int c = 0; c < 32; c++) o += gr[c] * W[c * 512 + j];
    red[j] = o;
    __syncthreads();
    for (int s = 256; s > 0; s >>= 1) {
        if (j < s) red[j] += red[j + s];
        __syncthreads();
    }
    float mu = red[0] / 512.f;
    __syncthreads();
    float d = o - mu;
    red[j] = d * d;
    __syncthreads();
    for (int s = 256; s > 0; s >>= 1) {
        if (j < s) red[j] += red[j + s];
        __syncthreads();
    }
    float var = red[0] / 512.f;
    out[b * 512 + j] = d * rsqrtf(var + 1e-5f) * lg[j] + lb[j];
}

extern "C" void kernel_launch(void* const* d_in, const int* in_sizes, int n_in,
                              void* d_out, int out_size) {
    const float* x      = (const float*)d_in[0];
    const float* pos    = (const float*)d_in[1];
    const float* emb_W  = (const float*)d_in[2];
    const float* si_W0  = (const float*)d_in[3];
    const float* si_W1  = (const float*)d_in[4];
    const float* si_W2  = (const float*)d_in[5];
    const float* rad_W1 = (const float*)d_in[6];
    const float* rad_b1 = (const float*)d_in[7];
    const float* rad_W2 = (const float*)d_in[8];
    const float* rad_b2 = (const float*)d_in[9];
    const float* rad_W3 = (const float*)d_in[10];
    const float* rad_b3 = (const float*)d_in[11];
    const float* pW1    = (const float*)d_in[12];
    const float* pb1    = (const float*)d_in[13];
    const float* pW2    = (const float*)d_in[14];
    const float* pb2    = (const float*)d_in[15];
    const float* pW3    = (const float*)d_in[16];
    const float* pb3    = (const float*)d_in[17];
    const float* out_W  = (const float*)d_in[18];
    const float* out_b  = (const float*)d_in[19];
    const float* ln_g   = (const float*)d_in[20];
    const float* ln_b   = (const float*)d_in[21];
    const int* ei       = (const int*)d_in[22];
    const int* batch    = (const int*)d_in[23];
    float* out = (float*)d_out;

    k_init_cg<<<1, 1>>>();
    k_edge_geom<<<EE / 256, 256>>>(pos, ei);
    k_embed<<<NN, 32>>>(x, emb_W);
    k_zero_h<<<(NN * 48 + 255) / 256, 256>>>();

    for (int l = 0; l < LL; l++) {
        int cur = l & 1;
        k_zero_agg<<<(NN * 48 + 255) / 256, 256>>>();
        k_radial<<<EE / 4, 256>>>(rad_W1 + l * 8 * 64, rad_b1 + l * 64,
                                  rad_W2 + l * 64 * 64, rad_b2 + l * 64);
        for (int c = 0; c < NCHUNK; c++) {
            k_gemm_chunk<<<dim3(27, EC / 128), 256>>>(c, rad_W3 + (size_t)l * 64 * 3456,
                                                      rad_b3 + l * 3456);
            k_msg<<<EC / 8, 256>>>(cur, c * EC, ei);
        }
        k_si<<<NN, 128>>>(cur, si_W0 + l * 32 * 32, si_W1 + l * 16 * 16, si_W2 + l * 8 * 8);
    }

    k_attmlp<<<NN, 128>>>(pW1, pb1, pW2, pb2, pW3, pb3);
    k_pool<<<BBATCH, 256>>>(batch);
    k_out<<<BBATCH, 512>>>(out_W, out_b, ln_g, ln_b, out);
}

// round 4
// speedup vs baseline: 1.2083x; 1.2083x over previous
#include <cuda_runtime.h>
#include <math.h>
#include <stdint.h>

#define NN 4096
#define EE 32768
#define EC 4096          // edges per chunk (w-chunk = 56.6 MB, L2-resident)
#define NCHUNK (EE / EC)
#define BBATCH 16
#define LL 4

#define SQ3C     1.73205080757f
#define SQ5C     2.23606797750f
#define INV_SQ3  0.57735026919f
#define INV_SQ5  0.44721359550f
#define INV_SQ75 0.36514837167f
#define A0C      0.13363062095f
#define A1C      0.20412414523f
#define A2C      0.27950849719f
#define ISQ32    0.17677669530f
#define ISQ16    0.25f
#define ISQ8     0.35355339059f
#define RBFN     0.79788458f

__constant__ float cQ[5][9] = {
    {0.f, 0.f, 0.86602540378f,  0.f, 0.f, 0.f,  0.86602540378f, 0.f, 0.f},
    {0.f, 0.86602540378f, 0.f,  0.86602540378f, 0.f, 0.f,  0.f, 0.f, 0.f},
    {-0.5f, 0.f, 0.f,  0.f, 1.f, 0.f,  0.f, 0.f, -0.5f},
    {0.f, 0.f, 0.f,  0.f, 0.f, 0.86602540378f,  0.f, 0.86602540378f, 0.f},
    {-0.86602540378f, 0.f, 0.f,  0.f, 0.f, 0.f,  0.f, 0.f, 0.86602540378f}};

__device__ float g_s1[EE * 3];
__device__ float g_s2[EE * 5];
__device__ float g_rbf[EE * 8];
__device__ float g_hid[EE * 64];
__device__ float g_w[(size_t)EC * 3456];
__device__ float g_h0[2][NN * 32];
__device__ float g_h1[2][NN * 48];
__device__ float g_h2[2][NN * 40];
__device__ float g_agg0[NN * 32];
__device__ float g_agg1[NN * 48];
__device__ float g_agg2[NN * 40];
__device__ float g_att[NN];
__device__ float g_pool[BBATCH * 32];
__device__ float g_C222[125];

__device__ __forceinline__ float siluf(float x) { return x / (1.f + expf(-x)); }

__device__ __forceinline__ uint32_t f2tf32(float x) {
    uint32_t u;
    asm("cvt.rna.tf32.f32 %0, %1;" : "=r"(u) : "f"(x));
    return u;
}

__global__ void k_init_cg() {
    if (threadIdx.x != 0 || blockIdx.x != 0) return;
    float T[125];
    float nrm = 0.f;
    for (int i = 0; i < 5; i++)
        for (int j = 0; j < 5; j++)
            for (int k = 0; k < 5; k++) {
                float s = 0.f;
                for (int a = 0; a < 3; a++)
                    for (int b = 0; b < 3; b++)
                        for (int c = 0; c < 3; c++)
                            s += cQ[i][a * 3 + b] * cQ[j][b * 3 + c] * cQ[k][c * 3 + a];
                T[(i * 5 + j) * 5 + k] = s;
                nrm += s * s;
            }
    nrm = sqrtf(nrm);
    for (int t = 0; t < 125; t++) g_C222[t] = T[t] / nrm;
}

__global__ void k_edge_geom(const float* __restrict__ pos, const int* __restrict__ ei) {
    int e = blockIdx.x * 256 + threadIdx.x;
    if (e >= EE) return;
    int s = ei[e], d = ei[EE + e];
    float rx = pos[d * 3 + 0] - pos[s * 3 + 0];
    float ry = pos[d * 3 + 1] - pos[s * 3 + 1];
    float rz = pos[d * 3 + 2] - pos[s * 3 + 2];
    float dist = sqrtf(rx * rx + ry * ry + rz * rz);
    dist = fmaxf(dist, 1e-6f);
    float nx = rx / dist, ny = ry / dist, nz = rz / dist;
    g_s1[e * 3 + 0] = SQ3C * nx;
    g_s1[e * 3 + 1] = SQ3C * ny;
    g_s1[e * 3 + 2] = SQ3C * nz;
    g_s2[e * 5 + 0] = SQ5C * (SQ3C * nx * nz);
    g_s2[e * 5 + 1] = SQ5C * (SQ3C * nx * ny);
    g_s2[e * 5 + 2] = SQ5C * (ny * ny - 0.5f * (nx * nx + nz * nz));
    g_s2[e * 5 + 3] = SQ5C * (SQ3C * ny * nz);
    g_s2[e * 5 + 4] = SQ5C * (0.5f * SQ3C * (nz * nz - nx * nx));
#pragma unroll
    for (int i = 0; i < 8; i++) {
        float c = 6.f * (float)i / 7.f;
        float t = dist - c;
        g_rbf[e * 8 + i] = expf(-2.f * t * t) * RBFN;
    }
}

__global__ void k_embed(const float* __restrict__ x, const float* __restrict__ W) {
    int n = blockIdx.x;
    int v = threadIdx.x;
    __shared__ float xr[64];
    for (int i = v; i < 64; i += 32) xr[i] = x[n * 64 + i];
    __syncthreads();
    float s = 0.f;
#pragma unroll 8
    for (int c = 0; c < 64; c++) s += xr[c] * W[c * 32 + v];
    g_h0[0][n * 32 + v] = s * 0.125f;
}

__global__ void k_zero_h() {
    int i = blockIdx.x * 256 + threadIdx.x;
    if (i < NN * 48) g_h1[0][i] = 0.f;
    if (i < NN * 40) g_h2[0][i] = 0.f;
}

__global__ void k_zero_agg() {
    int i = blockIdx.x * 256 + threadIdx.x;
    if (i < NN * 32) g_agg0[i] = 0.f;
    if (i < NN * 48) g_agg1[i] = 0.f;
    if (i < NN * 40) g_agg2[i] = 0.f;
}

__global__ void k_radial(const float* __restrict__ W1, const float* __restrict__ b1,
                         const float* __restrict__ W2, const float* __restrict__ b2) {
    int le = threadIdx.x >> 6;
    int t = threadIdx.x & 63;
    int e = blockIdx.x * 4 + le;
    __shared__ float sh[4][64];
    const float* r = g_rbf + e * 8;
    float z = b1[t];
#pragma unroll
    for (int i = 0; i < 8; i++) z += r[i] * W1[i * 64 + t];
    sh[le][t] = siluf(z);
    __syncthreads();
    float z2 = b2[t];
#pragma unroll 8
    for (int i = 0; i < 64; i++) z2 += sh[le][i] * W2[i * 64 + t];
    g_hid[e * 64 + t] = siluf(z2);
}

// ---------------- TF32 tensor-core GEMM ----------------
// g_w[EC,3456] = hid_chunk[EC,64] @ W3[64,3456] + bias
// block tile 128x64, K=64 fully resident. 8 warps as 4(row)x2(col),
// warp tile 32x32 = 2x4 m16n8k8 frags. XOR-swizzled smem.
__global__ void __launch_bounds__(256) k_gemm_tc(int chunk,
                                                 const float* __restrict__ Bm,
                                                 const float* __restrict__ bias) {
    __shared__ uint32_t As[128 * 64];   // 32 KB, As[row*64 + (col ^ ((row&7)<<2))]
    __shared__ uint32_t Bs[64 * 64];    // 16 KB, Bs[k*64 + (n ^ ((k&7)<<2))]
    int bx = blockIdx.x, by = blockIdx.y;
    int tid = threadIdx.x;
    const float* Ab = g_hid + (size_t)(chunk * EC + by * 128) * 64;
    const float* Bb = Bm + bx * 64;

    // load A tile (128x64): thread -> row=tid>>1, 32 cols
    {
        int row = tid >> 1, seg = (tid & 1) * 32;
        int sw = (row & 7) << 2;
        const float* src = Ab + row * 64 + seg;
#pragma unroll
        for (int q = 0; q < 8; q++) {
            float4 v = *(const float4*)(src + q * 4);
            uint4 u;
            u.x = f2tf32(v.x); u.y = f2tf32(v.y); u.z = f2tf32(v.z); u.w = f2tf32(v.w);
            *(uint4*)&As[row * 64 + ((seg + q * 4) ^ sw)] = u;
        }
    }
    // load B tile (64x64): thread -> k=tid>>2, 16 cols
    {
        int k = tid >> 2, nseg = (tid & 3) * 16;
        int sw = (k & 7) << 2;
        const float* src = Bb + (size_t)k * 3456 + nseg;
#pragma unroll
        for (int q = 0; q < 4; q++) {
            float4 v = *(const float4*)(src + q * 4);
            uint4 u;
            u.x = f2tf32(v.x); u.y = f2tf32(v.y); u.z = f2tf32(v.z); u.w = f2tf32(v.w);
            *(uint4*)&Bs[k * 64 + ((nseg + q * 4) ^ sw)] = u;
        }
    }
    __syncthreads();

    int lane = tid & 31, w = tid >> 5;
    int wr = w & 3, wc = w >> 2;       // wr: 4 row-groups of 32, wc: 2 col-groups of 32
    int g = lane >> 2, t = lane & 3;
    int sA = g << 2;

    float acc[2][4][4];
#pragma unroll
    for (int mi = 0; mi < 2; mi++)
#pragma unroll
        for (int ni = 0; ni < 4; ni++)
#pragma unroll
            for (int q = 0; q < 4; q++) acc[mi][ni][q] = 0.f;

#pragma unroll
    for (int kk = 0; kk < 8; kk++) {
        int k0 = kk * 8 + t;
        uint32_t a[2][4];
#pragma unroll
        for (int mi = 0; mi < 2; mi++) {
            int r0 = wr * 32 + mi * 16 + g;
            int c0 = k0 ^ sA;
            int c1 = (k0 + 4) ^ sA;
            a[mi][0] = As[r0 * 64 + c0];
            a[mi][1] = As[(r0 + 8) * 64 + c0];
            a[mi][2] = As[r0 * 64 + c1];
            a[mi][3] = As[(r0 + 8) * 64 + c1];
        }
        uint32_t b[4][2];
        int sb0 = t << 2, sb1 = (t + 4) << 2;
#pragma unroll
        for (int ni = 0; ni < 4; ni++) {
            int n0 = wc * 32 + ni * 8 + g;
            b[ni][0] = Bs[k0 * 64 + (n0 ^ sb0)];
            b[ni][1] = Bs[(k0 + 4) * 64 + (n0 ^ sb1)];
        }
#pragma unroll
        for (int mi = 0; mi < 2; mi++)
#pragma unroll
            for (int ni = 0; ni < 4; ni++) {
                asm volatile(
                    "mma.sync.aligned.m16n8k8.row.col.f32.tf32.tf32.f32 "
                    "{%0,%1,%2,%3}, {%4,%5,%6,%7}, {%8,%9}, {%0,%1,%2,%3};"
                    : "+f"(acc[mi][ni][0]), "+f"(acc[mi][ni][1]),
                      "+f"(acc[mi][ni][2]), "+f"(acc[mi][ni][3])
                    : "r"(a[mi][0]), "r"(a[mi][1]), "r"(a[mi][2]), "r"(a[mi][3]),
                      "r"(b[ni][0]), "r"(b[ni][1]));
            }
    }

    // epilogue: add bias, write to g_w (chunk-local rows)
#pragma unroll
    for (int ni = 0; ni < 4; ni++) {
        int c = bx * 64 + wc * 32 + ni * 8 + 2 * t;
        float bv0 = bias[c], bv1 = bias[c + 1];
#pragma unroll
        for (int mi = 0; mi < 2; mi++) {
            int r = by * 128 + wr * 32 + mi * 16 + g;
            float2 v0 = make_float2(acc[mi][ni][0] + bv0, acc[mi][ni][1] + bv1);
            float2 v1 = make_float2(acc[mi][ni][2] + bv0, acc[mi][ni][3] + bv1);
            *(float2*)(g_w + (size_t)r * 3456 + c) = v0;
            *(float2*)(g_w + (size_t)(r + 8) * 3456 + c) = v1;
        }
    }
}

__global__ void __launch_bounds__(256) k_msg(int cur, int e0, const int* __restrict__ ei) {
    __shared__ float S[8][400];
    int wid = threadIdx.x >> 5, lane = threadIdx.x & 31;
    int e = e0 + blockIdx.x * 8 + wid;
    float* P = S[wid];
    int src = ei[e], dst = ei[EE + e];
    const float* h0 = g_h0[cur];
    const float* h1 = g_h1[cur];
    const float* h2 = g_h2[cur];

    if (lane < 32) P[lane] = h0[src * 32 + lane];
    for (int i = lane; i < 48; i += 32) P[32 + i] = h1[src * 48 + i];
    for (int i = lane; i < 40; i += 32) P[80 + i] = h2[src * 40 + i];
    if (lane < 3) P[336 + lane] = g_s1[e * 3 + lane];
    if (lane < 5) P[339 + lane] = g_s2[e * 5 + lane];
    __syncwarp();

    if (lane < 9) {
        int i = lane / 3, j = lane % 3;
        float s = 0.f;
#pragma unroll
        for (int k = 0; k < 5; k++) s += P[339 + k] * cQ[k][i * 3 + j];
        P[344 + lane] = s;
    } else if (lane < 24) {
        int idx = lane - 9;
        int a = idx / 3, c = idx % 3;
        float s = 0.f;
#pragma unroll
        for (int b = 0; b < 3; b++) s += cQ[a][b * 3 + c] * P[336 + b];
        P[353 + idx] = s;
    } else {
        int u = lane - 24;
        float s = 0.f;
#pragma unroll
        for (int k = 0; k < 5; k++) s += P[80 + u * 5 + k] * P[339 + k];
        P[136 + u] = s * INV_SQ5;
    }
    __syncwarp();
    if (lane < 25) {
        int a = lane / 5, k = lane % 5;
        float s = 0.f;
#pragma unroll
        for (int b = 0; b < 5; b++) s += P[339 + b] * g_C222[(a * 5 + b) * 5 + k];
        P[368 + lane] = s;
    } else {
        int u = lane - 25;
        float s = 0.f;
#pragma unroll
        for (int i = 0; i < 3; i++) s += P[32 + u * 3 + i] * P[336 + i];
        P[120 + u] = s * INV_SQ3;
    }
    __syncwarp();
    if (lane < 9) {
        int u = lane + 7;
        float s = 0.f;
#pragma unroll
        for (int i = 0; i < 3; i++) s += P[32 + u * 3 + i] * P[336 + i];
        P[120 + u] = s * INV_SQ3;
    }
    __syncwarp();

    for (int idx = lane; idx < 192; idx += 32) {
        if (idx < 48) {
            int u = idx / 3, j = idx % 3;
            float s = 0.f;
#pragma unroll
            for (int i = 0; i < 3; i++) s += P[32 + u * 3 + i] * P[344 + i * 3 + j];
            P[144 + idx] = s * INV_SQ75;
        } else if (idx < 72) {
            int t = idx - 48;
            int u = t / 3, c = t % 3;
            float s = 0.f;
#pragma unroll
            for (int a = 0; a < 5; a++) s += P[80 + u * 5 + a] * P[353 + a * 3 + c];
            P[192 + t] = s * INV_SQ75;
        } else if (idx < 152) {
            int t = idx - 72;
            int u = t / 5, k = t % 5;
            float s = 0.f;
#pragma unroll
            for (int i = 0; i < 3; i++) s += P[32 + u * 3 + i] * P[353 + k * 3 + i];
            P[216 + t] = s * INV_SQ75;
        } else {
            int t = idx - 152;
            int u = t / 5, k = t % 5;
            float s = 0.f;
#pragma unroll
            for (int a = 0; a < 5; a++) s += P[80 + u * 5 + a] * P[368 + a * 5 + k];
            P[296 + t] = s;
        }
    }
    __syncwarp();

    const float* w = g_w + (size_t)(e - e0) * 3456;
    {
        int v = lane;
        float acc = 0.f;
#pragma unroll 8
        for (int u = 0; u < 32; u++) acc += w[u * 32 + v] * P[u];
#pragma unroll 8
        for (int u = 0; u < 16; u++) acc += w[1024 + u * 32 + v] * P[120 + u];
#pragma unroll
        for (int u = 0; u < 8; u++) acc += w[1536 + u * 32 + v] * P[136 + u];
        atomicAdd(&g_agg0[dst * 32 + v], A0C * acc);
    }
    if (lane < 16) {
        int v = lane;
        float p011 = 0.f;
#pragma unroll 8
        for (int u = 0; u < 32; u++) p011 += w[1792 + u * 16 + v] * P[u];
        float a1c[3] = {0.f, 0.f, 0.f};
        float b1c[3] = {0.f, 0.f, 0.f};
#pragma unroll 4
        for (int u = 0; u < 16; u++) {
            float wa = w[2304 + u * 16 + v];
            float wb = w[2560 + u * 16 + v];
#pragma unroll
            for (int j = 0; j < 3; j++) {
                a1c[j] += wa * P[32 + u * 3 + j];
                b1c[j] += wb * P[144 + u * 3 + j];
            }
        }
#pragma unroll
        for (int u = 0; u < 8; u++) {
            float wc = w[2816 + u * 16 + v];
#pragma unroll
            for (int j = 0; j < 3; j++) b1c[j] += wc * P[192 + u * 3 + j];
        }
#pragma unroll
        for (int j = 0; j < 3; j++) {
            float m = A1C * ((p011 * P[336 + j] + a1c[j]) * INV_SQ3 + b1c[j]);
            atomicAdd(&g_agg1[dst * 48 + v * 3 + j], m);
        }
    }
    if (lane < 8) {
        int v = lane;
        float p022 = 0.f;
#pragma unroll 8
        for (int u = 0; u < 32; u++) p022 += w[2944 + u * 8 + v] * P[u];
        float t2c[5] = {0.f, 0.f, 0.f, 0.f, 0.f};
#pragma unroll 4
        for (int u = 0; u < 16; u++) {
            float wa = w[3200 + u * 8 + v];
#pragma unroll
            for (int k = 0; k < 5; k++) t2c[k] += wa * P[216 + u * 5 + k];
        }
#pragma unroll
        for (int u = 0; u < 8; u++) {
            float wb = w[3328 + u * 8 + v];
            float wc = w[3392 + u * 8 + v];
#pragma unroll
            for (int k = 0; k < 5; k++)
                t2c[k] += wb * P[80 + u * 5 + k] * INV_SQ5 + wc * P[296 + u * 5 + k];
        }
#pragma unroll
        for (int k = 0; k < 5; k++) {
            float m = A2C * (p022 * P[339 + k] * INV_SQ5 + t2c[k]);
            atomicAdd(&g_agg2[dst * 40 + v * 5 + k], m);
        }
    }
}

__global__ void k_si(int cur, const float* __restrict__ siW0, const float* __restrict__ siW1,
                     const float* __restrict__ siW2) {
    int n = blockIdx.x, t = threadIdx.x;
    int nxt = cur ^ 1;
    __shared__ float o0[32], o1[48], o2[40];
    if (t < 32) o0[t] = g_h0[cur][n * 32 + t];
    else if (t < 80) o1[t - 32] = g_h1[cur][n * 48 + (t - 32)];
    else if (t < 120) o2[t - 80] = g_h2[cur][n * 40 + (t - 80)];
    __syncthreads();
    if (t < 32) {
        float s = 0.f;
#pragma unroll 8
        for (int u = 0; u < 32; u++) s += o0[u] * siW0[u * 32 + t];
        g_h0[nxt][n * 32 + t] = s * ISQ32 + g_agg0[n * 32 + t];
    } else if (t < 80) {
        int idx = t - 32;
        int v = idx / 3, i = idx % 3;
        float s = 0.f;
#pragma unroll 4
        for (int u = 0; u < 16; u++) s += o1[u * 3 + i] * siW1[u * 16 + v];
        g_h1[nxt][n * 48 + idx] = s * ISQ16 + g_agg1[n * 48 + idx];
    } else if (t < 120) {
        int idx = t - 80;
        int v = idx / 5, k = idx % 5;
        float s = 0.f;
#pragma unroll
        for (int u = 0; u < 8; u++) s += o2[u * 5 + k] * siW2[u * 8 + v];
        g_h2[nxt][n * 40 + idx] = s * ISQ8 + g_agg2[n * 40 + idx];
    }
}

__global__ void k_attmlp(const float* __restrict__ W1, const float* __restrict__ b1,
                         const float* __restrict__ W2, const float* __restrict__ b2,
                         const float* __restrict__ W3, const float* __restrict__ b3) {
    int n = blockIdx.x, t = threadIdx.x;
    __shared__ float hr[32], a1[128], red[128];
    if (t < 32) hr[t] = g_h0[0][n * 32 + t];
    __syncthreads();
    float z = b1[t];
#pragma unroll 8
    for (int c = 0; c < 32; c++) z += hr[c] * W1[c * 128 + t];
    a1[t] = siluf(z);
    __syncthreads();
    float z2 = b2[t];
#pragma unroll 8
    for (int c = 0; c < 128; c++) z2 += a1[c] * W2[c * 128 + t];
    z2 = siluf(z2);
    red[t] = z2 * W3[t];
    __syncthreads();
    for (int s = 64; s > 0; s >>= 1) {
        if (t < s) red[t] += red[t + s];
        __syncthreads();
    }
    if (t == 0) g_att[n] = red[0] + b3[0];
}

__global__ void k_pool(const int* __restrict__ batch) {
    int b = blockIdx.x, tid = threadIdx.x;
    __shared__ float red[256];
    __shared__ float gacc[32];
    __shared__ float s_amax, s_den;
    float lm = -1e30f;
    for (int n = tid; n < NN; n += 256)
        if (batch[n] == b) lm = fmaxf(lm, g_att[n]);
    red[tid] = lm;
    __syncthreads();
    for (int s = 128; s > 0; s >>= 1) {
        if (tid < s) red[tid] = fmaxf(red[tid], red[tid + s]);
        __syncthreads();
    }
    if (tid == 0) s_amax = red[0];
    if (tid < 32) gacc[tid] = 0.f;
    __syncthreads();
    float amax = s_amax;
    float lden = 0.f;
    for (int n = tid; n < NN; n += 256)
        if (batch[n] == b) {
            float ex = expf(g_att[n] - amax);
            lden += ex;
#pragma unroll
            for (int c = 0; c < 32; c++) atomicAdd(&gacc[c], ex * g_h0[0][n * 32 + c]);
        }
    red[tid] = lden;
    __syncthreads();
    for (int s = 128; s > 0; s >>= 1) {
        if (tid < s) red[tid] += red[tid + s];
        __syncthreads();
    }
    if (tid == 0) s_den = red[0];
    __syncthreads();
    if (tid < 32) g_pool[b * 32 + tid] = gacc[tid] / s_den;
}

__global__ void k_out(const float* __restrict__ W, const float* __restrict__ bo,
                      const float* __restrict__ lg, const float* __restrict__ lb,
                      float* __restrict__ out) {
    int b = blockIdx.x, j = threadIdx.x;
    __shared__ float gr[32];
    __shared__ float red[512];
    if (j < 32) gr[j] = g_pool[b * 32 + j];
    __syncthreads();
    float o = bo[j];
#pragma unroll 8
    for (int c = 0; c < 32; c++) o += gr[c] * W[c * 512 + j];
    red[j] = o;
    __syncthreads();
    for (int s = 256; s > 0; s >>= 1) {
        if (j < s) red[j] += red[j + s];
        __syncthreads();
    }
    float mu = red[0] / 512.f;
    __syncthreads();
    float d = o - mu;
    red[j] = d * d;
    __syncthreads();
    for (int s = 256; s > 0; s >>= 1) {
        if (j < s) red[j] += red[j + s];
        __syncthreads();
    }
    float var = red[0] / 512.f;
    out[b * 512 + j] = d * rsqrtf(var + 1e-5f) * lg[j] + lb[j];
}

extern "C" void kernel_launch(void* const* d_in, const int* in_sizes, int n_in,
                              void* d_out, int out_size) {
    const float* x      = (const float*)d_in[0];
    const float* pos    = (const float*)d_in[1];
    const float* emb_W  = (const float*)d_in[2];
    const float* si_W0  = (const float*)d_in[3];
    const float* si_W1  = (const float*)d_in[4];
    const float* si_W2  = (const float*)d_in[5];
    const float* rad_W1 = (const float*)d_in[6];
    const float* rad_b1 = (const float*)d_in[7];
    const float* rad_W2 = (const float*)d_in[8];
    const float* rad_b2 = (const float*)d_in[9];
    const float* rad_W3 = (const float*)d_in[10];
    const float* rad_b3 = (const float*)d_in[11];
    const float* pW1    = (const float*)d_in[12];
    const float* pb1    = (const float*)d_in[13];
    const float* pW2    = (const float*)d_in[14];
    const float* pb2    = (const float*)d_in[15];
    const float* pW3    = (const float*)d_in[16];
    const float* pb3    = (const float*)d_in[17];
    const float* out_W  = (const float*)d_in[18];
    const float* out_b  = (const float*)d_in[19];
    const float* ln_g   = (const float*)d_in[20];
    const float* ln_b   = (const float*)d_in[21];
    const int* ei       = (const int*)d_in[22];
    const int* batch    = (const int*)d_in[23];
    float* out = (float*)d_out;

    k_init_cg<<<1, 1>>>();
    k_edge_geom<<<EE / 256, 256>>>(pos, ei);
    k_embed<<<NN, 32>>>(x, emb_W);
    k_zero_h<<<(NN * 48 + 255) / 256, 256>>>();

    for (int l = 0; l < LL; l++) {
        int cur = l & 1;
        k_zero_agg<<<(NN * 48 + 255) / 256, 256>>>();
        k_radial<<<EE / 4, 256>>>(rad_W1 + l * 8 * 64, rad_b1 + l * 64,
                                  rad_W2 + l * 64 * 64, rad_b2 + l * 64);
        for (int c = 0; c < NCHUNK; c++) {
            k_gemm_tc<<<dim3(54, EC / 128), 256>>>(c, rad_W3 + (size_t)l * 64 * 3456,
                                                   rad_b3 + l * 3456);
            k_msg<<<EC / 8, 256>>>(cur, c * EC, ei);
        }
        k_si<<<NN, 128>>>(cur, si_W0 + l * 32 * 32, si_W1 + l * 16 * 16, si_W2 + l * 8 * 8);
    }

    k_attmlp<<<NN, 128>>>(pW1, pb1, pW2, pb2, pW3, pb3);
    k_pool<<<BBATCH, 256>>>(batch);
    k_out<<<BBATCH, 512>>>(out_W, out_b, ln_g, ln_b, out);
}

// round 6
// speedup vs baseline: 1.3551x; 1.1214x over previous
#include <cuda_runtime.h>
#include <cuda_fp16.h>
#include <math.h>
#include <stdint.h>

#define NN 4096
#define EE 32768
#define EC 8192          // edges per chunk (fp16 w-chunk = 56.6 MB, L2-resident)
#define NCHUNK (EE / EC)
#define BBATCH 16
#define LL 4

#define SQ3C     1.73205080757f
#define SQ5C     2.23606797750f
#define INV_SQ3  0.57735026919f
#define INV_SQ5  0.44721359550f
#define INV_SQ75 0.36514837167f
#define A0C      0.13363062095f
#define A1C      0.20412414523f
#define A2C      0.27950849719f
#define ISQ32    0.17677669530f
#define ISQ16    0.25f
#define ISQ8     0.35355339059f
#define RBFN     0.79788458f

__constant__ float cQ[5][9] = {
    {0.f, 0.f, 0.86602540378f,  0.f, 0.f, 0.f,  0.86602540378f, 0.f, 0.f},
    {0.f, 0.86602540378f, 0.f,  0.86602540378f, 0.f, 0.f,  0.f, 0.f, 0.f},
    {-0.5f, 0.f, 0.f,  0.f, 1.f, 0.f,  0.f, 0.f, -0.5f},
    {0.f, 0.f, 0.f,  0.f, 0.f, 0.86602540378f,  0.f, 0.86602540378f, 0.f},
    {-0.86602540378f, 0.f, 0.f,  0.f, 0.f, 0.f,  0.f, 0.f, 0.86602540378f}};

__device__ float g_s1[EE * 3];
__device__ float g_s2[EE * 5];
__device__ float g_rbf[EE * 8];
__device__ float g_hid[EE * 64];
__device__ __half g_wh[(size_t)EC * 3456];
__device__ float g_h0[2][NN * 32];
__device__ float g_h1[2][NN * 48];
__device__ float g_h2[2][NN * 40];
__device__ float g_agg0[NN * 32];
__device__ float g_agg1[NN * 48];
__device__ float g_agg2[NN * 40];
__device__ float g_att[NN];
__device__ float g_pool[BBATCH * 32];
__device__ float g_C222[125];

__device__ __forceinline__ float siluf(float x) { return x / (1.f + expf(-x)); }

__device__ __forceinline__ uint32_t f2tf32(float x) {
    uint32_t u;
    asm("cvt.rna.tf32.f32 %0, %1;" : "=r"(u) : "f"(x));
    return u;
}

// ---------------- edge geometry ----------------
__global__ void k_edge_geom(const float* __restrict__ pos, const int* __restrict__ ei) {
    int e = blockIdx.x * 256 + threadIdx.x;
    if (e >= EE) return;
    int s = ei[e], d = ei[EE + e];
    float rx = pos[d * 3 + 0] - pos[s * 3 + 0];
    float ry = pos[d * 3 + 1] - pos[s * 3 + 1];
    float rz = pos[d * 3 + 2] - pos[s * 3 + 2];
    float dist = sqrtf(rx * rx + ry * ry + rz * rz);
    dist = fmaxf(dist, 1e-6f);
    float nx = rx / dist, ny = ry / dist, nz = rz / dist;
    g_s1[e * 3 + 0] = SQ3C * nx;
    g_s1[e * 3 + 1] = SQ3C * ny;
    g_s1[e * 3 + 2] = SQ3C * nz;
    g_s2[e * 5 + 0] = SQ5C * (SQ3C * nx * nz);
    g_s2[e * 5 + 1] = SQ5C * (SQ3C * nx * ny);
    g_s2[e * 5 + 2] = SQ5C * (ny * ny - 0.5f * (nx * nx + nz * nz));
    g_s2[e * 5 + 3] = SQ5C * (SQ3C * ny * nz);
    g_s2[e * 5 + 4] = SQ5C * (0.5f * SQ3C * (nz * nz - nx * nx));
#pragma unroll
    for (int i = 0; i < 8; i++) {
        float c = 6.f * (float)i / 7.f;
        float t = dist - c;
        g_rbf[e * 8 + i] = expf(-2.f * t * t) * RBFN;
    }
}

// ---------------- fused prologue: embed + zero h1/h2/agg + parallel CG init ----------------
// grid = NN+1 blocks, 128 threads.  block n<NN: node work.  block NN: C222.
__global__ void k_prologue(const float* __restrict__ x, const float* __restrict__ W) {
    int n = blockIdx.x, t = threadIdx.x;
    if (n < NN) {
        __shared__ float xr[64];
        if (t < 64) xr[t] = x[n * 64 + t];
        __syncthreads();
        if (t < 32) {
            float s = 0.f;
#pragma unroll 8
            for (int c = 0; c < 64; c++) s += xr[c] * W[c * 32 + t];
            g_h0[0][n * 32 + t] = s * 0.125f;
            g_agg0[n * 32 + t] = 0.f;
        }
        if (t < 48) { g_h1[0][n * 48 + t] = 0.f; g_agg1[n * 48 + t] = 0.f; }
        if (t < 40) { g_h2[0][n * 40 + t] = 0.f; g_agg2[n * 40 + t] = 0.f; }
    } else {
        // parallel C222: 125 threads, each 27 iterations, then block norm-reduce
        __shared__ float T[128];
        __shared__ float red[128];
        float v = 0.f;
        if (t < 125) {
            int i = t / 25, j = (t / 5) % 5, k = t % 5;
            for (int a = 0; a < 3; a++)
                for (int b = 0; b < 3; b++)
                    for (int c = 0; c < 3; c++)
                        v += cQ[i][a * 3 + b] * cQ[j][b * 3 + c] * cQ[k][c * 3 + a];
        }
        T[t] = v;
        red[t] = v * v;
        __syncthreads();
        for (int s = 64; s > 0; s >>= 1) {
            if (t < s) red[t] += red[t + s];
            __syncthreads();
        }
        float inv = rsqrtf(red[0]);
        if (t < 125) g_C222[t] = T[t] * inv;
    }
}

// ---------------- radial MLP ----------------
__global__ void k_radial(const float* __restrict__ W1, const float* __restrict__ b1,
                         const float* __restrict__ W2, const float* __restrict__ b2) {
    int le = threadIdx.x >> 6;
    int t = threadIdx.x & 63;
    int e = blockIdx.x * 4 + le;
    __shared__ float sh[4][64];
    const float* r = g_rbf + e * 8;
    float z = b1[t];
#pragma unroll
    for (int i = 0; i < 8; i++) z += r[i] * W1[i * 64 + t];
    sh[le][t] = siluf(z);
    __syncthreads();
    float z2 = b2[t];
#pragma unroll 8
    for (int i = 0; i < 64; i++) z2 += sh[le][i] * W2[i * 64 + t];
    g_hid[e * 64 + t] = siluf(z2);
}

// ---------------- TF32 tensor-core GEMM -> fp16 w ----------------
__global__ void __launch_bounds__(256) k_gemm_tc(int chunk,
                                                 const float* __restrict__ Bm,
                                                 const float* __restrict__ bias) {
    __shared__ uint32_t As[128 * 64];
    __shared__ uint32_t Bs[64 * 64];
    int bx = blockIdx.x, by = blockIdx.y;
    int tid = threadIdx.x;
    const float* Ab = g_hid + (size_t)(chunk * EC + by * 128) * 64;
    const float* Bb = Bm + bx * 64;

    {
        int row = tid >> 1, seg = (tid & 1) * 32;
        int sw = (row & 7) << 2;
        const float* src = Ab + row * 64 + seg;
#pragma unroll
        for (int q = 0; q < 8; q++) {
            float4 v = *(const float4*)(src + q * 4);
            uint4 u;
            u.x = f2tf32(v.x); u.y = f2tf32(v.y); u.z = f2tf32(v.z); u.w = f2tf32(v.w);
            *(uint4*)&As[row * 64 + ((seg + q * 4) ^ sw)] = u;
        }
    }
    {
        int k = tid >> 2, nseg = (tid & 3) * 16;
        int sw = (k & 7) << 2;
        const float* src = Bb + (size_t)k * 3456 + nseg;
#pragma unroll
        for (int q = 0; q < 4; q++) {
            float4 v = *(const float4*)(src + q * 4);
            uint4 u;
            u.x = f2tf32(v.x); u.y = f2tf32(v.y); u.z = f2tf32(v.z); u.w = f2tf32(v.w);
            *(uint4*)&Bs[k * 64 + ((nseg + q * 4) ^ sw)] = u;
        }
    }
    __syncthreads();

    int lane = tid & 31, w = tid >> 5;
    int wr = w & 3, wc = w >> 2;
    int g = lane >> 2, t = lane & 3;
    int sA = g << 2;

    float acc[2][4][4];
#pragma unroll
    for (int mi = 0; mi < 2; mi++)
#pragma unroll
        for (int ni = 0; ni < 4; ni++)
#pragma unroll
            for (int q = 0; q < 4; q++) acc[mi][ni][q] = 0.f;

#pragma unroll
    for (int kk = 0; kk < 8; kk++) {
        int k0 = kk * 8 + t;
        uint32_t a[2][4];
#pragma unroll
        for (int mi = 0; mi < 2; mi++) {
            int r0 = wr * 32 + mi * 16 + g;
            int c0 = k0 ^ sA;
            int c1 = (k0 + 4) ^ sA;
            a[mi][0] = As[r0 * 64 + c0];
            a[mi][1] = As[(r0 + 8) * 64 + c0];
            a[mi][2] = As[r0 * 64 + c1];
            a[mi][3] = As[(r0 + 8) * 64 + c1];
        }
        uint32_t b[4][2];
        int sb0 = t << 2, sb1 = (t + 4) << 2;
#pragma unroll
        for (int ni = 0; ni < 4; ni++) {
            int n0 = wc * 32 + ni * 8 + g;
            b[ni][0] = Bs[k0 * 64 + (n0 ^ sb0)];
            b[ni][1] = Bs[(k0 + 4) * 64 + (n0 ^ sb1)];
        }
#pragma unroll
        for (int mi = 0; mi < 2; mi++)
#pragma unroll
            for (int ni = 0; ni < 4; ni++) {
                asm volatile(
                    "mma.sync.aligned.m16n8k8.row.col.f32.tf32.tf32.f32 "
                    "{%0,%1,%2,%3}, {%4,%5,%6,%7}, {%8,%9}, {%0,%1,%2,%3};"
                    : "+f"(acc[mi][ni][0]), "+f"(acc[mi][ni][1]),
                      "+f"(acc[mi][ni][2]), "+f"(acc[mi][ni][3])
                    : "r"(a[mi][0]), "r"(a[mi][1]), "r"(a[mi][2]), "r"(a[mi][3]),
                      "r"(b[ni][0]), "r"(b[ni][1]));
            }
    }

#pragma unroll
    for (int ni = 0; ni < 4; ni++) {
        int c = bx * 64 + wc * 32 + ni * 8 + 2 * t;
        float bv0 = bias[c], bv1 = bias[c + 1];
#pragma unroll
        for (int mi = 0; mi < 2; mi++) {
            int r = by * 128 + wr * 32 + mi * 16 + g;
            __half2 v0 = __floats2half2_rn(acc[mi][ni][0] + bv0, acc[mi][ni][1] + bv1);
            __half2 v1 = __floats2half2_rn(acc[mi][ni][2] + bv0, acc[mi][ni][3] + bv1);
            *(__half2*)(g_wh + (size_t)r * 3456 + c) = v0;
            *(__half2*)(g_wh + (size_t)(r + 8) * 3456 + c) = v1;
        }
    }
}

// ---------------- message kernel (fp16 w) ----------------
__global__ void __launch_bounds__(256) k_msg(int cur, int e0, const int* __restrict__ ei) {
    __shared__ float S[8][400];
    int wid = threadIdx.x >> 5, lane = threadIdx.x & 31;
    int e = e0 + blockIdx.x * 8 + wid;
    float* P = S[wid];
    int src = ei[e], dst = ei[EE + e];
    const float* h0 = g_h0[cur];
    const float* h1 = g_h1[cur];
    const float* h2 = g_h2[cur];

    if (lane < 32) P[lane] = h0[src * 32 + lane];
    for (int i = lane; i < 48; i += 32) P[32 + i] = h1[src * 48 + i];
    for (int i = lane; i < 40; i += 32) P[80 + i] = h2[src * 40 + i];
    if (lane < 3) P[336 + lane] = g_s1[e * 3 + lane];
    if (lane < 5) P[339 + lane] = g_s2[e * 5 + lane];
    __syncwarp();

    if (lane < 9) {
        int i = lane / 3, j = lane % 3;
        float s = 0.f;
#pragma unroll
        for (int k = 0; k < 5; k++) s += P[339 + k] * cQ[k][i * 3 + j];
        P[344 + lane] = s;
    } else if (lane < 24) {
        int idx = lane - 9;
        int a = idx / 3, c = idx % 3;
        float s = 0.f;
#pragma unroll
        for (int b = 0; b < 3; b++) s += cQ[a][b * 3 + c] * P[336 + b];
        P[353 + idx] = s;
    } else {
        int u = lane - 24;
        float s = 0.f;
#pragma unroll
        for (int k = 0; k < 5; k++) s += P[80 + u * 5 + k] * P[339 + k];
        P[136 + u] = s * INV_SQ5;
    }
    __syncwarp();
    if (lane < 25) {
        int a = lane / 5, k = lane % 5;
        float s = 0.f;
#pragma unroll
        for (int b = 0; b < 5; b++) s += P[339 + b] * g_C222[(a * 5 + b) * 5 + k];
        P[368 + lane] = s;
    } else {
        int u = lane - 25;
        float s = 0.f;
#pragma unroll
        for (int i = 0; i < 3; i++) s += P[32 + u * 3 + i] * P[336 + i];
        P[120 + u] = s * INV_SQ3;
    }
    __syncwarp();
    if (lane < 9) {
        int u = lane + 7;
        float s = 0.f;
#pragma unroll
        for (int i = 0; i < 3; i++) s += P[32 + u * 3 + i] * P[336 + i];
        P[120 + u] = s * INV_SQ3;
    }
    __syncwarp();

    for (int idx = lane; idx < 192; idx += 32) {
        if (idx < 48) {
            int u = idx / 3, j = idx % 3;
            float s = 0.f;
#pragma unroll
            for (int i = 0; i < 3; i++) s += P[32 + u * 3 + i] * P[344 + i * 3 + j];
            P[144 + idx] = s * INV_SQ75;
        } else if (idx < 72) {
            int t = idx - 48;
            int u = t / 3, c = t % 3;
            float s = 0.f;
#pragma unroll
            for (int a = 0; a < 5; a++) s += P[80 + u * 5 + a] * P[353 + a * 3 + c];
            P[192 + t] = s * INV_SQ75;
        } else if (idx < 152) {
            int t = idx - 72;
            int u = t / 5, k = t % 5;
            float s = 0.f;
#pragma unroll
            for (int i = 0; i < 3; i++) s += P[32 + u * 3 + i] * P[353 + k * 3 + i];
            P[216 + t] = s * INV_SQ75;
        } else {
            int t = idx - 152;
            int u = t / 5, k = t % 5;
            float s = 0.f;
#pragma unroll
            for (int a = 0; a < 5; a++) s += P[80 + u * 5 + a] * P[368 + a * 5 + k];
            P[296 + t] = s;
        }
    }
    __syncwarp();

    const __half* w = g_wh + (size_t)(e - e0) * 3456;
    {
        int v = lane;
        float acc = 0.f;
#pragma unroll 8
        for (int u = 0; u < 32; u++) acc += __half2float(w[u * 32 + v]) * P[u];
#pragma unroll 8
        for (int u = 0; u < 16; u++) acc += __half2float(w[1024 + u * 32 + v]) * P[120 + u];
#pragma unroll
        for (int u = 0; u < 8; u++) acc += __half2float(w[1536 + u * 32 + v]) * P[136 + u];
        atomicAdd(&g_agg0[dst * 32 + v], A0C * acc);
    }
    if (lane < 16) {
        int v = lane;
        float p011 = 0.f;
#pragma unroll 8
        for (int u = 0; u < 32; u++) p011 += __half2float(w[1792 + u * 16 + v]) * P[u];
        float a1c[3] = {0.f, 0.f, 0.f};
        float b1c[3] = {0.f, 0.f, 0.f};
#pragma unroll 4
        for (int u = 0; u < 16; u++) {
            float wa = __half2float(w[2304 + u * 16 + v]);
            float wb = __half2float(w[2560 + u * 16 + v]);
#pragma unroll
            for (int j = 0; j < 3; j++) {
                a1c[j] += wa * P[32 + u * 3 + j];
                b1c[j] += wb * P[144 + u * 3 + j];
            }
        }
#pragma unroll
        for (int u = 0; u < 8; u++) {
            float wc = __half2float(w[2816 + u * 16 + v]);
#pragma unroll
            for (int j = 0; j < 3; j++) b1c[j] += wc * P[192 + u * 3 + j];
        }
#pragma unroll
        for (int j = 0; j < 3; j++) {
            float m = A1C * ((p011 * P[336 + j] + a1c[j]) * INV_SQ3 + b1c[j]);
            atomicAdd(&g_agg1[dst * 48 + v * 3 + j], m);
        }
    }
    if (lane < 8) {
        int v = lane;
        float p022 = 0.f;
#pragma unroll 8
        for (int u = 0; u < 32; u++) p022 += __half2float(w[2944 + u * 8 + v]) * P[u];
        float t2c[5] = {0.f, 0.f, 0.f, 0.f, 0.f};
#pragma unroll 4
        for (int u = 0; u < 16; u++) {
            float wa = __half2float(w[3200 + u * 8 + v]);
#pragma unroll
            for (int k = 0; k < 5; k++) t2c[k] += wa * P[216 + u * 5 + k];
        }
#pragma unroll
        for (int u = 0; u < 8; u++) {
            float wb = __half2float(w[3328 + u * 8 + v]);
            float wc = __half2float(w[3392 + u * 8 + v]);
#pragma unroll
            for (int k = 0; k < 5; k++)
                t2c[k] += wb * P[80 + u * 5 + k] * INV_SQ5 + wc * P[296 + u * 5 + k];
        }
#pragma unroll
        for (int k = 0; k < 5; k++) {
            float m = A2C * (p022 * P[339 + k] * INV_SQ5 + t2c[k]);
            atomicAdd(&g_agg2[dst * 40 + v * 5 + k], m);
        }
    }
}

// ---------------- self interaction + aggregate -> next buffers, zero agg ----------------
__global__ void k_si(int cur, const float* __restrict__ siW0, const float* __restrict__ siW1,
                     const float* __restrict__ siW2) {
    int n = blockIdx.x, t = threadIdx.x;
    int nxt = cur ^ 1;
    __shared__ float o0[32], o1[48], o2[40];
    if (t < 32) o0[t] = g_h0[cur][n * 32 + t];
    else if (t < 80) o1[t - 32] = g_h1[cur][n * 48 + (t - 32)];
    else if (t < 120) o2[t - 80] = g_h2[cur][n * 40 + (t - 80)];
    __syncthreads();
    if (t < 32) {
        float s = 0.f;
#pragma unroll 8
        for (int u = 0; u < 32; u++) s += o0[u] * siW0[u * 32 + t];
        g_h0[nxt][n * 32 + t] = s * ISQ32 + g_agg0[n * 32 + t];
        g_agg0[n * 32 + t] = 0.f;
    } else if (t < 80) {
        int idx = t - 32;
        int v = idx / 3, i = idx % 3;
        float s = 0.f;
#pragma unroll 4
        for (int u = 0; u < 16; u++) s += o1[u * 3 + i] * siW1[u * 16 + v];
        g_h1[nxt][n * 48 + idx] = s * ISQ16 + g_agg1[n * 48 + idx];
        g_agg1[n * 48 + idx] = 0.f;
    } else if (t < 120) {
        int idx = t - 80;
        int v = idx / 5, k = idx % 5;
        float s = 0.f;
#pragma unroll
        for (int u = 0; u < 8; u++) s += o2[u * 5 + k] * siW2[u * 8 + v];
        g_h2[nxt][n * 40 + idx] = s * ISQ8 + g_agg2[n * 40 + idx];
        g_agg2[n * 40 + idx] = 0.f;
    }
}

// ---------------- attention MLP ----------------
__global__ void k_attmlp(const float* __restrict__ W1, const float* __restrict__ b1,
                         const float* __restrict__ W2, const float* __restrict__ b2,
                         const float* __restrict__ W3, const float* __restrict__ b3) {
    int n = blockIdx.x, t = threadIdx.x;
    __shared__ float hr[32], a1[128], red[128];
    if (t < 32) hr[t] = g_h0[0][n * 32 + t];
    __syncthreads();
    float z = b1[t];
#pragma unroll 8
    for (int c = 0; c < 32; c++) z += hr[c] * W1[c * 128 + t];
    a1[t] = siluf(z);
    __syncthreads();
    float z2 = b2[t];
#pragma unroll 8
    for (int c = 0; c < 128; c++) z2 += a1[c] * W2[c * 128 + t];
    z2 = siluf(z2);
    red[t] = z2 * W3[t];
    __syncthreads();
    for (int s = 64; s > 0; s >>= 1) {
        if (t < s) red[t] += red[t + s];
        __syncthreads();
    }
    if (t == 0) g_att[n] = red[0] + b3[0];
}

// ---------------- pooling: register accum + warp-shuffle reduce ----------------
__global__ void k_pool(const int* __restrict__ batch) {
    int b = blockIdx.x, tid = threadIdx.x;  // 256 threads
    int lane = tid & 31, wrp = tid >> 5;
    __shared__ float red[256];
    __shared__ float gacc[32];
    __shared__ float s_amax, s_den;
    float lm = -1e30f;
    for (int n = tid; n < NN; n += 256)
        if (batch[n] == b) lm = fmaxf(lm, g_att[n]);
    red[tid] = lm;
    __syncthreads();
    for (int s = 128; s > 0; s >>= 1) {
        if (tid < s) red[tid] = fmaxf(red[tid], red[tid + s]);
        __syncthreads();
    }
    if (tid == 0) s_amax = red[0];
    if (tid < 32) gacc[tid] = 0.f;
    __syncthreads();
    float amax = s_amax;
    float lden = 0.f;
    float acc[32];
#pragma unroll
    for (int c = 0; c < 32; c++) acc[c] = 0.f;
    for (int n = tid; n < NN; n += 256)
        if (batch[n] == b) {
            float ex = expf(g_att[n] - amax);
            lden += ex;
#pragma unroll
            for (int c = 0; c < 32; c++) acc[c] += ex * g_h0[0][n * 32 + c];
        }
    // warp reduce each channel, then one atomic per warp per channel
#pragma unroll
    for (int c = 0; c < 32; c++) {
        float v = acc[c];
#pragma unroll
        for (int o = 16; o > 0; o >>= 1) v += __shfl_xor_sync(0xffffffff, v, o);
        if (lane == 0) atomicAdd(&gacc[c], v);
    }
    red[tid] = lden;
    __syncthreads();
    for (int s = 128; s > 0; s >>= 1) {
        if (tid < s) red[tid] += red[tid + s];
        __syncthreads();
    }
    if (tid == 0) s_den = red[0];
    __syncthreads();
    if (tid < 32) g_pool[b * 32 + tid] = gacc[tid] / s_den;
    (void)wrp;
}

// ---------------- final linear + layernorm ----------------
__global__ void k_out(const float* __restrict__ W, const float* __restrict__ bo,
                      const float* __restrict__ lg, const float* __restrict__ lb,
                      float* __restrict__ out) {
    int b = blockIdx.x, j = threadIdx.x;
    __shared__ float gr[32];
    __shared__ float red[512];
    if (j < 32) gr[j] = g_pool[b * 32 + j];
    __syncthreads();
    float o = bo[j];
#pragma unroll 8
    for (int c = 0; c < 32; c++) o += gr[c] * W[c * 512 + j];
    red[j] = o;
    __syncthreads();
    for (int s = 256; s > 0; s >>= 1) {
        if (j < s) red[j] += red[j + s];
        __syncthreads();
    }
    float mu = red[0] / 512.f;
    __syncthreads();
    float d = o - mu;
    red[j] = d * d;
    __syncthreads();
    for (int s = 256; s > 0; s >>= 1) {
        if (j < s) red[j] += red[j + s];
        __syncthreads();
    }
    float var = red[0] / 512.f;
    out[b * 512 + j] = d * rsqrtf(var + 1e-5f) * lg[j] + lb[j];
}

extern "C" void kernel_launch(void* const* d_in, const int* in_sizes, int n_in,
                              void* d_out, int out_size) {
    const float* x      = (const float*)d_in[0];
    const float* pos    = (const float*)d_in[1];
    const float* emb_W  = (const float*)d_in[2];
    const float* si_W0  = (const float*)d_in[3];
    const float* si_W1  = (const float*)d_in[4];
    const float* si_W2  = (const float*)d_in[5];
    const float* rad_W1 = (const float*)d_in[6];
    const float* rad_b1 = (const float*)d_in[7];
    const float* rad_W2 = (const float*)d_in[8];
    const float* rad_b2 = (const float*)d_in[9];
    const float* rad_W3 = (const float*)d_in[10];
    const float* rad_b3 = (const float*)d_in[11];
    const float* pW1    = (const float*)d_in[12];
    const float* pb1    = (const float*)d_in[13];
    const float* pW2    = (const float*)d_in[14];
    const float* pb2    = (const float*)d_in[15];
    const float* pW3    = (const float*)d_in[16];
    const float* pb3    = (const float*)d_in[17];
    const float* out_W  = (const float*)d_in[18];
    const float* out_b  = (const float*)d_in[19];
    const float* ln_g   = (const float*)d_in[20];
    const float* ln_b   = (const float*)d_in[21];
    const int* ei       = (const int*)d_in[22];
    const int* batch    = (const int*)d_in[23];
    float* out = (float*)d_out;

    // launch order chosen so ncu's profiled slot (#4) lands on k_gemm_tc
    k_edge_geom<<<EE / 256, 256>>>(pos, ei);                       // 1
    k_prologue<<<NN + 1, 128>>>(x, emb_W);                         // 2

    for (int l = 0; l < LL; l++) {
        int cur = l & 1;
        k_radial<<<EE / 4, 256>>>(rad_W1 + l * 8 * 64, rad_b1 + l * 64,
                                  rad_W2 + l * 64 * 64, rad_b2 + l * 64);  // 3 (l=0)
        for (int c = 0; c < NCHUNK; c++) {
            k_gemm_tc<<<dim3(54, EC / 128), 256>>>(c, rad_W3 + (size_t)l * 64 * 3456,
                                                   rad_b3 + l * 3456);      // 4 (l=0,c=0)
            k_msg<<<EC / 8, 256>>>(cur, c * EC, ei);                        // 5 (l=0,c=0)
        }
        k_si<<<NN, 128>>>(cur, si_W0 + l * 32 * 32, si_W1 + l * 16 * 16, si_W2 + l * 8 * 8);
    }

    k_attmlp<<<NN, 128>>>(pW1, pb1, pW2, pb2, pW3, pb3);
    k_pool<<<BBATCH, 256>>>(batch);
    k_out<<<BBATCH, 512>>>(out_W, out_b, ln_g, ln_b, out);
}

// round 8
// speedup vs baseline: 2.3960x; 1.7682x over previous
#include <cuda_runtime.h>
#include <cuda_fp16.h>
#include <math.h>
#include <stdint.h>

#define NN 4096
#define EE 32768
#define EC 8192
#define NCHUNK (EE / EC)
#define BBATCH 16
#define LL 4

#define SQ3C     1.73205080757f
#define SQ5C     2.23606797750f
#define INV_SQ3  0.57735026919f
#define INV_SQ5  0.44721359550f
#define INV_SQ75 0.36514837167f
#define A0C      0.13363062095f
#define A1C      0.20412414523f
#define A2C      0.27950849719f
#define ISQ32    0.17677669530f
#define ISQ16    0.25f
#define ISQ8     0.35355339059f
#define RBFN     0.79788458f

__constant__ float cQ[5][9] = {
    {0.f, 0.f, 0.86602540378f,  0.f, 0.f, 0.f,  0.86602540378f, 0.f, 0.f},
    {0.f, 0.86602540378f, 0.f,  0.86602540378f, 0.f, 0.f,  0.f, 0.f, 0.f},
    {-0.5f, 0.f, 0.f,  0.f, 1.f, 0.f,  0.f, 0.f, -0.5f},
    {0.f, 0.f, 0.f,  0.f, 0.f, 0.86602540378f,  0.f, 0.86602540378f, 0.f},
    {-0.86602540378f, 0.f, 0.f,  0.f, 0.f, 0.f,  0.f, 0.f, 0.86602540378f}};

// path segments: offset, U(in-mul), V(out-mul); permuted layout stores [v][u]
__constant__ int segOff[12] = {0, 1024, 1536, 1792, 2304, 2560, 2816, 2944, 3200, 3328, 3392, 3456};
__constant__ int segU[11]   = {32, 16, 8, 32, 16, 16, 8, 32, 16, 8, 8};
__constant__ int segV[11]   = {32, 32, 32, 16, 16, 16, 16, 8, 8, 8, 8};

__device__ float  g_s1[EE * 3];
__device__ float  g_s2[EE * 5];
__device__ float  g_rbf[EE * 8];
__device__ __half g_hidh[EE * 64];
__device__ __half g_w3h[(size_t)LL * 64 * 3456];   // permuted fp16 W3
__device__ float  g_b3p[LL * 3456];                // permuted bias
__device__ __half g_wh[(size_t)EC * 3456];
__device__ float  g_h0[2][NN * 32];
__device__ float  g_h1[2][NN * 48];
__device__ float  g_h2[2][NN * 40];
__device__ float  g_agg0[NN * 32];
__device__ float  g_agg1[NN * 48];
__device__ float  g_agg2[NN * 40];
__device__ float  g_att[NN];
__device__ float  g_pool[BBATCH * 32];
__device__ float  g_C222[125];

__device__ __forceinline__ float siluf(float x) { return x / (1.f + expf(-x)); }

#define LDSM_X4(r0, r1, r2, r3, addr)                                              \
    asm volatile("ldmatrix.sync.aligned.m8n8.x4.shared.b16 {%0,%1,%2,%3}, [%4];"   \
                 : "=r"(r0), "=r"(r1), "=r"(r2), "=r"(r3) : "r"(addr))
#define LDSM_X4_T(r0, r1, r2, r3, addr)                                                 \
    asm volatile("ldmatrix.sync.aligned.m8n8.x4.trans.shared.b16 {%0,%1,%2,%3}, [%4];"  \
                 : "=r"(r0), "=r"(r1), "=r"(r2), "=r"(r3) : "r"(addr))
#define MMA_F16(d, a, b0, b1)                                                      \
    asm volatile("mma.sync.aligned.m16n8k16.row.col.f32.f16.f16.f32 "              \
                 "{%0,%1,%2,%3}, {%4,%5,%6,%7}, {%8,%9}, {%0,%1,%2,%3};"           \
                 : "+f"(d[0]), "+f"(d[1]), "+f"(d[2]), "+f"(d[3])                  \
                 : "r"(a[0]), "r"(a[1]), "r"(a[2]), "r"(a[3]), "r"(b0), "r"(b1))

// ---------------- edge geometry ----------------
__global__ void k_edge_geom(const float* __restrict__ pos, const int* __restrict__ ei) {
    int e = blockIdx.x * 256 + threadIdx.x;
    if (e >= EE) return;
    int s = ei[e], d = ei[EE + e];
    float rx = pos[d * 3 + 0] - pos[s * 3 + 0];
    float ry = pos[d * 3 + 1] - pos[s * 3 + 1];
    float rz = pos[d * 3 + 2] - pos[s * 3 + 2];
    float dist = sqrtf(rx * rx + ry * ry + rz * rz);
    dist = fmaxf(dist, 1e-6f);
    float nx = rx / dist, ny = ry / dist, nz = rz / dist;
    g_s1[e * 3 + 0] = SQ3C * nx;
    g_s1[e * 3 + 1] = SQ3C * ny;
    g_s1[e * 3 + 2] = SQ3C * nz;
    g_s2[e * 5 + 0] = SQ5C * (SQ3C * nx * nz);
    g_s2[e * 5 + 1] = SQ5C * (SQ3C * nx * ny);
    g_s2[e * 5 + 2] = SQ5C * (ny * ny - 0.5f * (nx * nx + nz * nz));
    g_s2[e * 5 + 3] = SQ5C * (SQ3C * ny * nz);
    g_s2[e * 5 + 4] = SQ5C * (0.5f * SQ3C * (nz * nz - nx * nx));
#pragma unroll
    for (int i = 0; i < 8; i++) {
        float c = 6.f * (float)i / 7.f;
        float t = dist - c;
        g_rbf[e * 8 + i] = expf(-2.f * t * t) * RBFN;
    }
}

// ---------------- W3 permute + fp16 convert (+ permuted bias) ----------------
__global__ void k_prep(const float* __restrict__ W3, const float* __restrict__ b3) {
    int idx = blockIdx.x * 256 + threadIdx.x;
    if (idx >= LL * 64 * 3456) return;
    int l = idx / (64 * 3456);
    int rem = idx % (64 * 3456);
    int k = rem / 3456;
    int cp = rem % 3456;
    int seg = 0;
    while (cp >= segOff[seg + 1]) seg++;
    int local = cp - segOff[seg];
    int U = segU[seg], V = segV[seg];
    int v = local / U, u = local % U;
    int c = segOff[seg] + u * V + v;
    g_w3h[idx] = __float2half(W3[(size_t)l * 221184 + (size_t)k * 3456 + c]);
    if (k == 0) g_b3p[l * 3456 + cp] = b3[l * 3456 + c];
}

// ---------------- fused prologue: embed + zero + parallel CG init ----------------
__global__ void k_prologue(const float* __restrict__ x, const float* __restrict__ W) {
    int n = blockIdx.x, t = threadIdx.x;
    if (n < NN) {
        __shared__ float xr[64];
        if (t < 64) xr[t] = x[n * 64 + t];
        __syncthreads();
        if (t < 32) {
            float s = 0.f;
#pragma unroll 8
            for (int c = 0; c < 64; c++) s += xr[c] * W[c * 32 + t];
            g_h0[0][n * 32 + t] = s * 0.125f;
            g_agg0[n * 32 + t] = 0.f;
        }
        if (t < 48) { g_h1[0][n * 48 + t] = 0.f; g_agg1[n * 48 + t] = 0.f; }
        if (t < 40) { g_h2[0][n * 40 + t] = 0.f; g_agg2[n * 40 + t] = 0.f; }
    } else {
        __shared__ float T[128];
        __shared__ float red[128];
        float v = 0.f;
        if (t < 125) {
            int i = t / 25, j = (t / 5) % 5, k = t % 5;
            for (int a = 0; a < 3; a++)
                for (int b = 0; b < 3; b++)
                    for (int c = 0; c < 3; c++)
                        v += cQ[i][a * 3 + b] * cQ[j][b * 3 + c] * cQ[k][c * 3 + a];
        }
        T[t] = v;
        red[t] = v * v;
        __syncthreads();
        for (int s = 64; s > 0; s >>= 1) {
            if (t < s) red[t] += red[t + s];
            __syncthreads();
        }
        float inv = rsqrtf(red[0]);
        if (t < 125) g_C222[t] = T[t] * inv;
    }
}

// ---------------- radial MLP (fp16 output) ----------------
__global__ void k_radial(const float* __restrict__ W1, const float* __restrict__ b1,
                         const float* __restrict__ W2, const float* __restrict__ b2) {
    int le = threadIdx.x >> 6;
    int t = threadIdx.x & 63;
    int e = blockIdx.x * 4 + le;
    __shared__ float sh[4][64];
    const float* r = g_rbf + e * 8;
    float z = b1[t];
#pragma unroll
    for (int i = 0; i < 8; i++) z += r[i] * W1[i * 64 + t];
    sh[le][t] = siluf(z);
    __syncthreads();
    float z2 = b2[t];
#pragma unroll 8
    for (int i = 0; i < 64; i++) z2 += sh[le][i] * W2[i * 64 + t];
    g_hidh[e * 64 + t] = __float2half(siluf(z2));
}

// ---------------- fp16 tensor-core GEMM: g_wh = hid[EC,64] @ W3p[64,3456] + b3p ----------------
// block tile 128x128, K=64 resident. 8 warps 4(M)x2(N), warp tile 32x64, m16n8k16.
__global__ void __launch_bounds__(256) k_gemm_h(int chunk, int l) {
    __shared__ __align__(16) __half As[128 * 64];   // row-major, 8 chunks/row, XOR swizzle
    __shared__ __align__(16) __half Bs[64 * 128];   // row=k, 16 chunks/row, XOR swizzle
    int bx = blockIdx.x, by = blockIdx.y;
    int tid = threadIdx.x;
    const __half* Bm = g_w3h + (size_t)l * 221184;
    const float* bias = g_b3p + l * 3456;

    // load A: 128 rows x 64 halves(128 B)
    {
        int row = tid >> 1;
        int cq0 = (tid & 1) * 4;
        const uint4* src = (const uint4*)(g_hidh + (size_t)(chunk * EC + by * 128 + row) * 64);
#pragma unroll
        for (int q = 0; q < 4; q++) {
            int ck = cq0 + q;
            *(uint4*)&As[row * 64 + ((ck ^ (row & 7)) * 8)] = src[ck];
        }
    }
    // load B: 64 rows(k) x 128 halves(256 B)
    {
        int k = tid >> 2;
        int bq0 = (tid & 3) * 4;
        const uint4* src = (const uint4*)(Bm + (size_t)k * 3456 + bx * 128);
#pragma unroll
        for (int q = 0; q < 4; q++) {
            int ck = bq0 + q;
            *(uint4*)&Bs[k * 128 + ((ck ^ (k & 7)) * 8)] = src[ck];
        }
    }
    __syncthreads();

    int lane = tid & 31, w = tid >> 5;
    int wr = w & 3, wc = w >> 2;
    int off = lane & 7, qd = lane >> 3;
    int rowSel = ((qd & 1) << 3) + off;   // +0/+8 within 16
    int chkSel = qd >> 1;                 // second k/n chunk

    uint32_t aBase = (uint32_t)__cvta_generic_to_shared(As);
    uint32_t bBase = (uint32_t)__cvta_generic_to_shared(Bs);

    float acc[2][8][4];
#pragma unroll
    for (int mi = 0; mi < 2; mi++)
#pragma unroll
        for (int n8 = 0; n8 < 8; n8++)
#pragma unroll
            for (int q = 0; q < 4; q++) acc[mi][n8][q] = 0.f;

#pragma unroll
    for (int kk = 0; kk < 4; kk++) {
        uint32_t a[2][4];
#pragma unroll
        for (int mi = 0; mi < 2; mi++) {
            int row = wr * 32 + mi * 16 + rowSel;
            int chk = kk * 2 + chkSel;
            uint32_t ad = aBase + (uint32_t)(row * 64 + ((chk ^ (row & 7)) * 8)) * 2;
            LDSM_X4(a[mi][0], a[mi][1], a[mi][2], a[mi][3], ad);
        }
        int krow = kk * 16 + rowSel;
        int ksw = krow & 7;
        uint32_t b[4][4];
#pragma unroll
        for (int j = 0; j < 4; j++) {
            int chk = wc * 8 + j * 2 + chkSel;
            uint32_t bd = bBase + (uint32_t)(krow * 128 + ((chk ^ ksw) * 8)) * 2;
            LDSM_X4_T(b[j][0], b[j][1], b[j][2], b[j][3], bd);
        }
#pragma unroll
        for (int mi = 0; mi < 2; mi++)
#pragma unroll
            for (int j = 0; j < 4; j++) {
                MMA_F16(acc[mi][j * 2 + 0], a[mi], b[j][0], b[j][1]);
                MMA_F16(acc[mi][j * 2 + 1], a[mi], b[j][2], b[j][3]);
            }
    }

    // epilogue: bias + fp16 store
    int g = lane >> 2, t4 = lane & 3;
#pragma unroll
    for (int n8 = 0; n8 < 8; n8++) {
        int c = bx * 128 + wc * 64 + n8 * 8 + 2 * t4;
        float2 bv = *(const float2*)(bias + c);
#pragma unroll
        for (int mi = 0; mi < 2; mi++) {
            int r = by * 128 + wr * 32 + mi * 16 + g;
            *(__half2*)(g_wh + (size_t)r * 3456 + c) =
                __floats2half2_rn(acc[mi][n8][0] + bv.x, acc[mi][n8][1] + bv.y);
            *(__half2*)(g_wh + (size_t)(r + 8) * 3456 + c) =
                __floats2half2_rn(acc[mi][n8][2] + bv.x, acc[mi][n8][3] + bv.y);
        }
    }
}

// ---------------- message kernel: vectorized loads from permuted fp16 w ----------------
__global__ void __launch_bounds__(256) k_msg(int cur, int e0, const int* __restrict__ ei) {
    __shared__ float S[8][400];
    int wid = threadIdx.x >> 5, lane = threadIdx.x & 31;
    int e = e0 + blockIdx.x * 8 + wid;
    float* P = S[wid];
    int src = ei[e], dst = ei[EE + e];
    const float* h0 = g_h0[cur];
    const float* h1 = g_h1[cur];
    const float* h2 = g_h2[cur];

    if (lane < 32) P[lane] = h0[src * 32 + lane];
    for (int i = lane; i < 48; i += 32) P[32 + i] = h1[src * 48 + i];
    for (int i = lane; i < 40; i += 32) P[80 + i] = h2[src * 40 + i];
    if (lane < 3) P[336 + lane] = g_s1[e * 3 + lane];
    if (lane < 5) P[339 + lane] = g_s2[e * 5 + lane];
    __syncwarp();

    if (lane < 9) {
        int i = lane / 3, j = lane % 3;
        float s = 0.f;
#pragma unroll
        for (int k = 0; k < 5; k++) s += P[339 + k] * cQ[k][i * 3 + j];
        P[344 + lane] = s;
    } else if (lane < 24) {
        int idx = lane - 9;
        int a = idx / 3, c = idx % 3;
        float s = 0.f;
#pragma unroll
        for (int b = 0; b < 3; b++) s += cQ[a][b * 3 + c] * P[336 + b];
        P[353 + idx] = s;
    } else {
        int u = lane - 24;
        float s = 0.f;
#pragma unroll
        for (int k = 0; k < 5; k++) s += P[80 + u * 5 + k] * P[339 + k];
        P[136 + u] = s * INV_SQ5;
    }
    __syncwarp();
    if (lane < 25) {
        int a = lane / 5, k = lane % 5;
        float s = 0.f;
#pragma unroll
        for (int b = 0; b < 5; b++) s += P[339 + b] * g_C222[(a * 5 + b) * 5 + k];
        P[368 + lane] = s;
    } else {
        int u = lane - 25;
        float s = 0.f;
#pragma unroll
        for (int i = 0; i < 3; i++) s += P[32 + u * 3 + i] * P[336 + i];
        P[120 + u] = s * INV_SQ3;
    }
    __syncwarp();
    if (lane < 9) {
        int u = lane + 7;
        float s = 0.f;
#pragma unroll
        for (int i = 0; i < 3; i++) s += P[32 + u * 3 + i] * P[336 + i];
        P[120 + u] = s * INV_SQ3;
    }
    __syncwarp();

    for (int idx = lane; idx < 192; idx += 32) {
        if (idx < 48) {
            int u = idx / 3, j = idx % 3;
            float s = 0.f;
#pragma unroll
            for (int i = 0; i < 3; i++) s += P[32 + u * 3 + i] * P[344 + i * 3 + j];
            P[144 + idx] = s * INV_SQ75;
        } else if (idx < 72) {
            int t = idx - 48;
            int u = t / 3, c = t % 3;
            float s = 0.f;
#pragma unroll
            for (int a = 0; a < 5; a++) s += P[80 + u * 5 + a] * P[353 + a * 3 + c];
            P[192 + t] = s * INV_SQ75;
        } else if (idx < 152) {
            int t = idx - 72;
            int u = t / 5, k = t % 5;
            float s = 0.f;
#pragma unroll
            for (int i = 0; i < 3; i++) s += P[32 + u * 3 + i] * P[353 + k * 3 + i];
            P[216 + t] = s * INV_SQ75;
        } else {
            int t = idx - 152;
            int u = t / 5, k = t % 5;
            float s = 0.f;
#pragma unroll
            for (int a = 0; a < 5; a++) s += P[80 + u * 5 + a] * P[368 + a * 5 + k];
            P[296 + t] = s;
        }
    }
    __syncwarp();

    const __half* wp = g_wh + (size_t)(e - e0) * 3456;
    // ---- m0: all 32 lanes, v = lane ----
    {
        int v = lane;
        float acc = 0.f;
        const uint4* q0 = (const uint4*)(wp + v * 32);          // w000T [v][32u]
#pragma unroll
        for (int b = 0; b < 4; b++) {
            uint4 x = q0[b];
            const __half2* hh = (const __half2*)&x;
#pragma unroll
            for (int i = 0; i < 4; i++) {
                float2 f = __half22float2(hh[i]);
                int u = b * 8 + i * 2;
                acc += f.x * P[u] + f.y * P[u + 1];
            }
        }
        const uint4* q1 = (const uint4*)(wp + 1024 + v * 16);   // w110T [v][16u]
#pragma unroll
        for (int b = 0; b < 2; b++) {
            uint4 x = q1[b];
            const __half2* hh = (const __half2*)&x;
#pragma unroll
            for (int i = 0; i < 4; i++) {
                float2 f = __half22float2(hh[i]);
                int u = b * 8 + i * 2;
                acc += f.x * P[120 + u] + f.y * P[120 + u + 1];
            }
        }
        {
            uint4 x = *(const uint4*)(wp + 1536 + v * 8);       // w220T [v][8u]
            const __half2* hh = (const __half2*)&x;
#pragma unroll
            for (int i = 0; i < 4; i++) {
                float2 f = __half22float2(hh[i]);
                int u = i * 2;
                acc += f.x * P[136 + u] + f.y * P[136 + u + 1];
            }
        }
        atomicAdd(&g_agg0[dst * 32 + v], A0C * acc);
    }
    // ---- m1: lanes 0-15, v = lane ----
    if (lane < 16) {
        int v = lane;
        float p011 = 0.f;
        const uint4* q0 = (const uint4*)(wp + 1792 + v * 32);   // w011T [v][32u]
#pragma unroll
        for (int b = 0; b < 4; b++) {
            uint4 x = q0[b];
            const __half2* hh = (const __half2*)&x;
#pragma unroll
            for (int i = 0; i < 4; i++) {
                float2 f = __half22float2(hh[i]);
                int u = b * 8 + i * 2;
                p011 += f.x * P[u] + f.y * P[u + 1];
            }
        }
        float a1c[3] = {0.f, 0.f, 0.f};
        float b1c[3] = {0.f, 0.f, 0.f};
        const uint4* qa = (const uint4*)(wp + 2304 + v * 16);   // w101T [v][16u]
#pragma unroll
        for (int b = 0; b < 2; b++) {
            uint4 x = qa[b];
            const __half2* hh = (const __half2*)&x;
#pragma unroll
            for (int i = 0; i < 4; i++) {
                float2 f = __half22float2(hh[i]);
                int u = b * 8 + i * 2;
#pragma unroll
                for (int j = 0; j < 3; j++)
                    a1c[j] += f.x * P[32 + u * 3 + j] + f.y * P[32 + (u + 1) * 3 + j];
            }
        }
        const uint4* qb = (const uint4*)(wp + 2560 + v * 16);   // w121T [v][16u]
#pragma unroll
        for (int b = 0; b < 2; b++) {
            uint4 x = qb[b];
            const __half2* hh = (const __half2*)&x;
#pragma unroll
            for (int i = 0; i < 4; i++) {
                float2 f = __half22float2(hh[i]);
                int u = b * 8 + i * 2;
#pragma unroll
                for (int j = 0; j < 3; j++)
                    b1c[j] += f.x * P[144 + u * 3 + j] + f.y * P[144 + (u + 1) * 3 + j];
            }
        }
        {
            uint4 x = *(const uint4*)(wp + 2816 + v * 8);       // w211T [v][8u]
            const __half2* hh = (const __half2*)&x;
#pragma unroll
            for (int i = 0; i < 4; i++) {
                float2 f = __half22float2(hh[i]);
                int u = i * 2;
#pragma unroll
                for (int j = 0; j < 3; j++)
                    b1c[j] += f.x * P[192 + u * 3 + j] + f.y * P[192 + (u + 1) * 3 + j];
            }
        }
#pragma unroll
        for (int j = 0; j < 3; j++) {
            float m = A1C * ((p011 * P[336 + j] + a1c[j]) * INV_SQ3 + b1c[j]);
            atomicAdd(&g_agg1[dst * 48 + v * 3 + j], m);
        }
    }
    // ---- m2: lanes 0-7, v = lane ----
    if (lane < 8) {
        int v = lane;
        float p022 = 0.f;
        const uint4* q0 = (const uint4*)(wp + 2944 + v * 32);   // w022T [v][32u]
#pragma unroll
        for (int b = 0; b < 4; b++) {
            uint4 x = q0[b];
            const __half2* hh = (const __half2*)&x;
#pragma unroll
            for (int i = 0; i < 4; i++) {
                float2 f = __half22float2(hh[i]);
                int u = b * 8 + i * 2;
                p022 += f.x * P[u] + f.y * P[u + 1];
            }
        }
        float t2c[5] = {0.f, 0.f, 0.f, 0.f, 0.f};
        const uint4* qa = (const uint4*)(wp + 3200 + v * 16);   // w112T [v][16u]
#pragma unroll
        for (int b = 0; b < 2; b++) {
            uint4 x = qa[b];
            const __half2* hh = (const __half2*)&x;
#pragma unroll
            for (int i = 0; i < 4; i++) {
                float2 f = __half22float2(hh[i]);
                int u = b * 8 + i * 2;
#pragma unroll
                for (int k = 0; k < 5; k++)
                    t2c[k] += f.x * P[216 + u * 5 + k] + f.y * P[216 + (u + 1) * 5 + k];
            }
        }
        {
            uint4 x = *(const uint4*)(wp + 3328 + v * 8);       // w202T [v][8u]
            const __half2* hh = (const __half2*)&x;
#pragma unroll
            for (int i = 0; i < 4; i++) {
                float2 f = __half22float2(hh[i]);
                int u = i * 2;
#pragma unroll
                for (int k = 0; k < 5; k++)
                    t2c[k] += (f.x * P[80 + u * 5 + k] + f.y * P[80 + (u + 1) * 5 + k]) * INV_SQ5;
            }
        }
        {
            uint4 x = *(const uint4*)(wp + 3392 + v * 8);       // w222T [v][8u]
            const __half2* hh = (const __half2*)&x;
#pragma unroll
            for (int i = 0; i < 4; i++) {
                float2 f = __half22float2(hh[i]);
                int u = i * 2;
#pragma unroll
                for (int k = 0; k < 5; k++)
                    t2c[k] += f.x * P[296 + u * 5 + k] + f.y * P[296 + (u + 1) * 5 + k];
            }
        }
#pragma unroll
        for (int k = 0; k < 5; k++) {
            float m = A2C * (p022 * P[339 + k] * INV_SQ5 + t2c[k]);
            atomicAdd(&g_agg2[dst * 40 + v * 5 + k], m);
        }
    }
}

// ---------------- self interaction + aggregate, rezero agg ----------------
__global__ void k_si(int cur, const float* __restrict__ siW0, const float* __restrict__ siW1,
                     const float* __restrict__ siW2) {
    int n = blockIdx.x, t = threadIdx.x;
    int nxt = cur ^ 1;
    __shared__ float o0[32], o1[48], o2[40];
    if (t < 32) o0[t] = g_h0[cur][n * 32 + t];
    else if (t < 80) o1[t - 32] = g_h1[cur][n * 48 + (t - 32)];
    else if (t < 120) o2[t - 80] = g_h2[cur][n * 40 + (t - 80)];
    __syncthreads();
    if (t < 32) {
        float s = 0.f;
#pragma unroll 8
        for (int u = 0; u < 32; u++) s += o0[u] * siW0[u * 32 + t];
        g_h0[nxt][n * 32 + t] = s * ISQ32 + g_agg0[n * 32 + t];
        g_agg0[n * 32 + t] = 0.f;
    } else if (t < 80) {
        int idx = t - 32;
        int v = idx / 3, i = idx % 3;
        float s = 0.f;
#pragma unroll 4
        for (int u = 0; u < 16; u++) s += o1[u * 3 + i] * siW1[u * 16 + v];
        g_h1[nxt][n * 48 + idx] = s * ISQ16 + g_agg1[n * 48 + idx];
        g_agg1[n * 48 + idx] = 0.f;
    } else if (t < 120) {
        int idx = t - 80;
        int v = idx / 5, k = idx % 5;
        float s = 0.f;
#pragma unroll
        for (int u = 0; u < 8; u++) s += o2[u * 5 + k] * siW2[u * 8 + v];
        g_h2[nxt][n * 40 + idx] = s * ISQ8 + g_agg2[n * 40 + idx];
        g_agg2[n * 40 + idx] = 0.f;
    }
}

// ---------------- attention MLP ----------------
__global__ void k_attmlp(const float* __restrict__ W1, const float* __restrict__ b1,
                         const float* __restrict__ W2, const float* __restrict__ b2,
                         const float* __restrict__ W3, const float* __restrict__ b3) {
    int n = blockIdx.x, t = threadIdx.x;
    __shared__ float hr[32], a1[128], red[128];
    if (t < 32) hr[t] = g_h0[0][n * 32 + t];
    __syncthreads();
    float z = b1[t];
#pragma unroll 8
    for (int c = 0; c < 32; c++) z += hr[c] * W1[c * 128 + t];
    a1[t] = siluf(z);
    __syncthreads();
    float z2 = b2[t];
#pragma unroll 8
    for (int c = 0; c < 128; c++) z2 += a1[c] * W2[c * 128 + t];
    z2 = siluf(z2);
    red[t] = z2 * W3[t];
    __syncthreads();
    for (int s = 64; s > 0; s >>= 1) {
        if (t < s) red[t] += red[t + s];
        __syncthreads();
    }
    if (t == 0) g_att[n] = red[0] + b3[0];
}

// ---------------- pooling ----------------
__global__ void k_pool(const int* __restrict__ batch) {
    int b = blockIdx.x, tid = threadIdx.x;
    int lane = tid & 31;
    __shared__ float red[256];
    __shared__ float gacc[32];
    __shared__ float s_amax, s_den;
    float lm = -1e30f;
    for (int n = tid; n < NN; n += 256)
        if (batch[n] == b) lm = fmaxf(lm, g_att[n]);
    red[tid] = lm;
    __syncthreads();
    for (int s = 128; s > 0; s >>= 1) {
        if (tid < s) red[tid] = fmaxf(red[tid], red[tid + s]);
        __syncthreads();
    }
    if (tid == 0) s_amax = red[0];
    if (tid < 32) gacc[tid] = 0.f;
    __syncthreads();
    float amax = s_amax;
    float lden = 0.f;
    float acc[32];
#pragma unroll
    for (int c = 0; c < 32; c++) acc[c] = 0.f;
    for (int n = tid; n < NN; n += 256)
        if (batch[n] == b) {
            float ex = expf(g_att[n] - amax);
            lden += ex;
#pragma unroll
            for (int c = 0; c < 32; c++) acc[c] += ex * g_h0[0][n * 32 + c];
        }
#pragma unroll
    for (int c = 0; c < 32; c++) {
        float v = acc[c];
#pragma unroll
        for (int o = 16; o > 0; o >>= 1) v += __shfl_xor_sync(0xffffffff, v, o);
        if (lane == 0) atomicAdd(&gacc[c], v);
    }
    red[tid] = lden;
    __syncthreads();
    for (int s = 128; s > 0; s >>= 1) {
        if (tid < s) red[tid] += red[tid + s];
        __syncthreads();
    }
    if (tid == 0) s_den = red[0];
    __syncthreads();
    if (tid < 32) g_pool[b * 32 + tid] = gacc[tid] / s_den;
}

// ---------------- final linear + layernorm ----------------
__global__ void k_out(const float* __restrict__ W, const float* __restrict__ bo,
                      const float* __restrict__ lg, const float* __restrict__ lb,
                      float* __restrict__ out) {
    int b = blockIdx.x, j = threadIdx.x;
    __shared__ float gr[32];
    __shared__ float red[512];
    if (j < 32) gr[j] = g_pool[b * 32 + j];
    __syncthreads();
    float o = bo[j];
#pragma unroll 8
    for (int c = 0; c < 32; c++) o += gr[c] * W[c * 512 + j];
    red[j] = o;
    __syncthreads();
    for (int s = 256; s > 0; s >>= 1) {
        if (j < s) red[j] += red[j + s];
        __syncthreads();
    }
    float mu = red[0] / 512.f;
    __syncthreads();
    float d = o - mu;
    red[j] = d * d;
    __syncthreads();
    for (int s = 256; s > 0; s >>= 1) {
        if (j < s) red[j] += red[j + s];
        __syncthreads();
    }
    float var = red[0] / 512.f;
    out[b * 512 + j] = d * rsqrtf(var + 1e-5f) * lg[j] + lb[j];
}

extern "C" void kernel_launch(void* const* d_in, const int* in_sizes, int n_in,
                              void* d_out, int out_size) {
    const float* x      = (const float*)d_in[0];
    const float* pos    = (const float*)d_in[1];
    const float* emb_W  = (const float*)d_in[2];
    const float* si_W0  = (const float*)d_in[3];
    const float* si_W1  = (const float*)d_in[4];
    const float* si_W2  = (const float*)d_in[5];
    const float* rad_W1 = (const float*)d_in[6];
    const float* rad_b1 = (const float*)d_in[7];
    const float* rad_W2 = (const float*)d_in[8];
    const float* rad_b2 = (const float*)d_in[9];
    const float* rad_W3 = (const float*)d_in[10];
    const float* rad_b3 = (const float*)d_in[11];
    const float* pW1    = (const float*)d_in[12];
    const float* pb1    = (const float*)d_in[13];
    const float* pW2    = (const float*)d_in[14];
    const float* pb2    = (const float*)d_in[15];
    const float* pW3    = (const float*)d_in[16];
    const float* pb3    = (const float*)d_in[17];
    const float* out_W  = (const float*)d_in[18];
    const float* out_b  = (const float*)d_in[19];
    const float* ln_g   = (const float*)d_in[20];
    const float* ln_b   = (const float*)d_in[21];
    const int* ei       = (const int*)d_in[22];
    const int* batch    = (const int*)d_in[23];
    float* out = (float*)d_out;

    // order chosen so ncu capture slot (index 5) = k_msg
    k_edge_geom<<<EE / 256, 256>>>(pos, ei);                      // 0
    k_prep<<<(LL * 64 * 3456 + 255) / 256, 256>>>(rad_W3, rad_b3);// 1
    k_prologue<<<NN + 1, 128>>>(x, emb_W);                        // 2

    for (int l = 0; l < LL; l++) {
        int cur = l & 1;
        k_radial<<<EE / 4, 256>>>(rad_W1 + l * 8 * 64, rad_b1 + l * 64,
                                  rad_W2 + l * 64 * 64, rad_b2 + l * 64);  // 3 (l=0)
        for (int c = 0; c < NCHUNK; c++) {
            k_gemm_h<<<dim3(27, EC / 128), 256>>>(c, l);                   // 4 (l=0,c=0)
            k_msg<<<EC / 8, 256>>>(cur, c * EC, ei);                       // 5 (l=0,c=0)
        }
        k_si<<<NN, 128>>>(cur, si_W0 + l * 32 * 32, si_W1 + l * 16 * 16, si_W2 + l * 8 * 8);
    }

    k_attmlp<<<NN, 128>>>(pW1, pb1, pW2, pb2, pW3, pb3);
    k_pool<<<BBATCH, 256>>>(batch);
    k_out<<<BBATCH, 512>>>(out_W, out_b, ln_g, ln_b, out);
}